// round 1
// baseline (speedup 1.0000x reference)
#include <cuda_runtime.h>

#define N_NODES 100000
#define N_EDGES 1200000
#define HID 64

// ---------------- device scratch (no allocations allowed) ----------------
__device__ int   g_cnt[N_NODES];
__device__ int   g_rowstart[N_NODES + 1];
__device__ int   g_cursor[N_NODES];
__device__ int   g_esrc[N_EDGES];
__device__ float g_h[(size_t)N_NODES * HID];
__device__ float g_z[(size_t)N_NODES * HID];
__device__ int   g_is64;

// ---------------- dtype detection for edge_index (int64 vs int32) --------
__global__ void detect_kernel(const void* ei) {
    if (threadIdx.x == 0 && blockIdx.x == 0) {
        const long long* p = (const long long*)ei;
        int ok = 1;
        for (int i = 0; i < 256; i++) {
            long long v = p[i];
            if (v < 0 || v >= N_NODES) { ok = 0; break; }
        }
        g_is64 = ok;
    }
}

__device__ __forceinline__ int load_idx(const void* ei, long long i, int is64) {
    if (is64) return (int)((const long long*)ei)[i];
    return ((const int*)ei)[i];
}

// ---------------- CSR build ----------------
__global__ void zero_cnt_kernel() {
    int i = blockIdx.x * blockDim.x + threadIdx.x;
    if (i < N_NODES) g_cnt[i] = 0;
}

__global__ void hist_kernel(const void* __restrict__ ei) {
    int is64 = g_is64;
    int e = blockIdx.x * blockDim.x + threadIdx.x;
    if (e < N_EDGES) {
        int dst = load_idx(ei, (long long)N_EDGES + e, is64);
        atomicAdd(&g_cnt[dst], 1);
    }
}

__global__ void scan_kernel() {
    __shared__ int s[1024];
    int t = threadIdx.x;
    const int chunk = (N_NODES + 1023) / 1024;  // 98
    int lo = t * chunk;
    int hi = lo + chunk;
    if (lo > N_NODES) lo = N_NODES;
    if (hi > N_NODES) hi = N_NODES;
    int sum = 0;
    for (int i = lo; i < hi; i++) sum += g_cnt[i];
    s[t] = sum;
    __syncthreads();
    // Hillis-Steele inclusive scan
    for (int off = 1; off < 1024; off <<= 1) {
        int v = (t >= off) ? s[t - off] : 0;
        __syncthreads();
        s[t] += v;
        __syncthreads();
    }
    int run = (t == 0) ? 0 : s[t - 1];
    for (int i = lo; i < hi; i++) {
        g_rowstart[i] = run;
        g_cursor[i] = run;
        run += g_cnt[i];
    }
    if (t == 1023) g_rowstart[N_NODES] = s[1023];
}

__global__ void fill_kernel(const void* __restrict__ ei) {
    int is64 = g_is64;
    int e = blockIdx.x * blockDim.x + threadIdx.x;
    if (e < N_EDGES) {
        int dst = load_idx(ei, (long long)N_EDGES + e, is64);
        int src = load_idx(ei, (long long)e, is64);
        int p = atomicAdd(&g_cursor[dst], 1);
        g_esrc[p] = src;
    }
}

// ---------------- SAGE layer (mean-agg + dual GEMM + LN + ReLU) ----------
// layer==0: in = x (arg), out = g_h.  layer==1: in = g_h, out = g_z.
__global__ void __launch_bounds__(256) sage_kernel(
    const float* __restrict__ x0, int layer,
    const float* __restrict__ wl, const float* __restrict__ wr,
    const float* __restrict__ bias, const float* __restrict__ lng,
    const float* __restrict__ lnb)
{
    __shared__ float wl_s[64 * 64], wr_s[64 * 64];
    __shared__ float mean_s[8][64], x_s[8][64];
    __shared__ float b_s[64], g_s[64], bb_s[64];

    const float* xin = (layer == 0) ? x0 : g_h;
    float* xout = (layer == 0) ? g_h : g_z;

    int tid = threadIdx.x;
    for (int i = tid; i < 64 * 64; i += 256) { wl_s[i] = wl[i]; wr_s[i] = wr[i]; }
    if (tid < 64) { b_s[tid] = bias[tid]; g_s[tid] = lng[tid]; bb_s[tid] = lnb[tid]; }
    __syncthreads();

    int w = tid >> 5, lane = tid & 31;

    for (int base = blockIdx.x * 8; base < N_NODES; base += gridDim.x * 8) {
        int node = base + w;
        if (node < N_NODES) {
            int rs = g_rowstart[node], re = g_rowstart[node + 1];
            float a0 = 0.f, a1 = 0.f;
            for (int i = rs; i < re; i++) {
                int src = g_esrc[i];
                const float* xp = xin + (size_t)src * 64;
                a0 += xp[lane];
                a1 += xp[lane + 32];
            }
            float inv = 1.f / (float)max(re - rs, 1);
            const float* xn = xin + (size_t)node * 64;
            mean_s[w][lane]      = a0 * inv;
            mean_s[w][lane + 32] = a1 * inv;
            x_s[w][lane]      = xn[lane];
            x_s[w][lane + 32] = xn[lane + 32];
        }
        __syncwarp();
        if (node < N_NODES) {
            float o0 = b_s[lane], o1 = b_s[lane + 32];
            #pragma unroll 8
            for (int k = 0; k < 64; k++) {
                float m = mean_s[w][k], xv = x_s[w][k];
                o0 += m * wl_s[k * 64 + lane]      + xv * wr_s[k * 64 + lane];
                o1 += m * wl_s[k * 64 + lane + 32] + xv * wr_s[k * 64 + lane + 32];
            }
            // layernorm over 64 features (2 per lane)
            float ssum = o0 + o1;
            #pragma unroll
            for (int off = 16; off > 0; off >>= 1) ssum += __shfl_xor_sync(0xffffffffu, ssum, off);
            float mu = ssum * (1.f / 64.f);
            float d0 = o0 - mu, d1 = o1 - mu;
            float vsum = d0 * d0 + d1 * d1;
            #pragma unroll
            for (int off = 16; off > 0; off >>= 1) vsum += __shfl_xor_sync(0xffffffffu, vsum, off);
            float rstd = rsqrtf(vsum * (1.f / 64.f) + 1e-5f);
            float r0 = d0 * rstd * g_s[lane]      + bb_s[lane];
            float r1 = d1 * rstd * g_s[lane + 32] + bb_s[lane + 32];
            xout[(size_t)node * 64 + lane]      = fmaxf(r0, 0.f);
            xout[(size_t)node * 64 + lane + 32] = fmaxf(r1, 0.f);
        }
        __syncwarp();
    }
}

// ---------------- Edge classifier MLP ------------------------------------
// warp processes 4 edges; transposed weights in dynamic SMEM.
// repr = [z_src(64) | z_dst(64) | z_src*z_dst(64) | edge_attr(32)] (224, pad 228)
#define ETILE 4
#define CW1T_STRIDE 228
#define CW2T_STRIDE 65

// dynamic smem layout (floats):
//   cw1t: 64*228       = 14592
//   cw2t: 32*65        = 2080   -> 16672
//   cb1 : 64                    -> 16736
//   cb2 : 32                    -> 16768
//   cw3 : 32                    -> 16800
//   repr: 8*4*228      = 7296   -> 24096
//   h1  : 8*4*64       = 2048   -> 26144 floats = 104576 bytes
#define EDGE_SMEM_FLOATS 26144
#define EDGE_SMEM_BYTES (EDGE_SMEM_FLOATS * 4)

extern __shared__ float sm_edge[];

__global__ void __launch_bounds__(256) edge_mlp_kernel(
    const void* __restrict__ ei, const float* __restrict__ ea,
    const float* __restrict__ cw1, const float* __restrict__ cb1,
    const float* __restrict__ cw2, const float* __restrict__ cb2,
    const float* __restrict__ cw3, const float* __restrict__ cb3,
    float* __restrict__ out)
{
    float* cw1t = sm_edge;                       // [64][228] (row f, col k)
    float* cw2t = cw1t + 64 * CW1T_STRIDE;       // [32][65]  (row j, col f)
    float* cb1s = cw2t + 32 * CW2T_STRIDE;
    float* cb2s = cb1s + 64;
    float* cw3s = cb2s + 32;
    float* reprs = cw3s + 32;                    // [32 edges][228]
    float* h1s   = reprs + 32 * 228;             // [32 edges][64]

    int tid = threadIdx.x;
    for (int i = tid; i < 224 * 64; i += 256) {
        int k = i >> 6, f = i & 63;
        cw1t[f * CW1T_STRIDE + k] = cw1[i];
    }
    for (int i = tid; i < 64 * 32; i += 256) {
        int f = i >> 5, j = i & 31;
        cw2t[j * CW2T_STRIDE + f] = cw2[i];
    }
    if (tid < 64) cb1s[tid] = cb1[tid];
    if (tid < 32) { cb2s[tid] = cb2[tid]; cw3s[tid] = cw3[tid]; }
    __syncthreads();

    const int is64 = g_is64;
    const float cb3v = cb3[0];
    int w = tid >> 5, lane = tid & 31;
    float* myrepr = reprs + w * (ETILE * 228);
    float* myh1 = h1s + w * (ETILE * 64);

    for (int blockbase = blockIdx.x * 32; blockbase < N_EDGES; blockbase += gridDim.x * 32) {
        int e0 = blockbase + w * ETILE;
        int ne = N_EDGES - e0;
        if (ne > ETILE) ne = ETILE;
        if (ne < 0) ne = 0;

        // ---- gather into smem repr ----
        for (int t = 0; t < ne; t++) {
            int e = e0 + t;
            int src = load_idx(ei, (long long)e, is64);
            int dst = load_idx(ei, (long long)N_EDGES + e, is64);
            float* rp = myrepr + t * 228;
            float2 a = ((const float2*)(g_z + (size_t)src * 64))[lane];
            float2 b = ((const float2*)(g_z + (size_t)dst * 64))[lane];
            ((float2*)(rp))[lane] = a;
            ((float2*)(rp + 64))[lane] = b;
            float2 p; p.x = a.x * b.x; p.y = a.y * b.y;
            ((float2*)(rp + 128))[lane] = p;
            if (lane < 16)
                ((float2*)(rp + 192))[lane] = ((const float2*)(ea + (size_t)e * 32))[lane];
        }
        __syncwarp();

        // ---- h1 = relu(repr @ cw1 + cb1): lane -> features (lane, lane+32) ----
        float acc[ETILE][2];
        #pragma unroll
        for (int t = 0; t < ETILE; t++) { acc[t][0] = cb1s[lane]; acc[t][1] = cb1s[lane + 32]; }
        const float4* w0 = (const float4*)(cw1t + lane * CW1T_STRIDE);
        const float4* w1 = (const float4*)(cw1t + (lane + 32) * CW1T_STRIDE);
        #pragma unroll 4
        for (int k4 = 0; k4 < 56; k4++) {
            float4 u = w0[k4], v = w1[k4];
            #pragma unroll
            for (int t = 0; t < ETILE; t++) {
                float4 r = ((const float4*)(myrepr + t * 228))[k4];
                acc[t][0] += r.x * u.x + r.y * u.y + r.z * u.z + r.w * u.w;
                acc[t][1] += r.x * v.x + r.y * v.y + r.z * v.z + r.w * v.w;
            }
        }
        #pragma unroll
        for (int t = 0; t < ETILE; t++) {
            myh1[t * 64 + lane]      = fmaxf(acc[t][0], 0.f);
            myh1[t * 64 + lane + 32] = fmaxf(acc[t][1], 0.f);
        }
        __syncwarp();

        // ---- h2 = relu(h1 @ cw2 + cb2); logit = h2 @ cw3 + cb3 ----
        #pragma unroll
        for (int t = 0; t < ETILE; t++) {
            float h2 = cb2s[lane];
            const float* h1p = myh1 + t * 64;
            const float* w2p = cw2t + lane * CW2T_STRIDE;
            #pragma unroll 8
            for (int f = 0; f < 64; f++) h2 += h1p[f] * w2p[f];
            h2 = fmaxf(h2, 0.f);
            float part = h2 * cw3s[lane];
            #pragma unroll
            for (int off = 16; off > 0; off >>= 1) part += __shfl_xor_sync(0xffffffffu, part, off);
            if (lane == 0 && t < ne) out[e0 + t] = part + cb3v;
        }
        __syncwarp();
    }
}

// ---------------- launch ----------------
extern "C" void kernel_launch(void* const* d_in, const int* in_sizes, int n_in,
                              void* d_out, int out_size)
{
    const float* x   = (const float*)d_in[0];
    const void*  ei  = (const void*)d_in[1];
    const float* ea  = (const float*)d_in[2];
    const float* wl0 = (const float*)d_in[3];
    const float* wr0 = (const float*)d_in[4];
    const float* b0  = (const float*)d_in[5];
    const float* g0  = (const float*)d_in[6];
    const float* bb0 = (const float*)d_in[7];
    const float* wl1 = (const float*)d_in[8];
    const float* wr1 = (const float*)d_in[9];
    const float* b1  = (const float*)d_in[10];
    const float* g1  = (const float*)d_in[11];
    const float* bb1 = (const float*)d_in[12];
    const float* cw1 = (const float*)d_in[13];
    const float* cb1 = (const float*)d_in[14];
    const float* cw2 = (const float*)d_in[15];
    const float* cb2 = (const float*)d_in[16];
    const float* cw3 = (const float*)d_in[17];
    const float* cb3 = (const float*)d_in[18];
    float* out = (float*)d_out;

    const int GRID_SAGE = 912;   // 6 blocks/SM-ish for latency hiding
    const int GRID_EDGE = 304;   // 2 blocks/SM (smem-limited)

    detect_kernel<<<1, 32>>>(ei);
    zero_cnt_kernel<<<(N_NODES + 255) / 256, 256>>>();
    hist_kernel<<<(N_EDGES + 255) / 256, 256>>>(ei);
    scan_kernel<<<1, 1024>>>();
    fill_kernel<<<(N_EDGES + 255) / 256, 256>>>(ei);

    sage_kernel<<<GRID_SAGE, 256>>>(x, 0, wl0, wr0, b0, g0, bb0);
    sage_kernel<<<GRID_SAGE, 256>>>(x, 1, wl1, wr1, b1, g1, bb1);

    cudaFuncSetAttribute(edge_mlp_kernel,
                         cudaFuncAttributeMaxDynamicSharedMemorySize, EDGE_SMEM_BYTES);
    edge_mlp_kernel<<<GRID_EDGE, 256, EDGE_SMEM_BYTES>>>(
        ei, ea, cw1, cb1, cw2, cb2, cw3, cb3, out);
}

// round 2
// speedup vs baseline: 1.8167x; 1.8167x over previous
#include <cuda_runtime.h>

#define N_NODES 100000
#define N_EDGES 1200000
#define HID 64

// ---------------- device scratch (no allocations allowed) ----------------
__device__ int   g_cnt[N_NODES];
__device__ int   g_rowstart[N_NODES + 1];
__device__ int   g_cursor[N_NODES];
__device__ int   g_bsum[128];
__device__ int   g_boff[128];
__device__ int   g_esrc[N_EDGES];
__device__ float g_h[(size_t)N_NODES * HID];
__device__ float g_z[(size_t)N_NODES * HID];
__device__ float g_A[(size_t)N_NODES * HID];   // z @ Ws + cb1
__device__ float g_B[(size_t)N_NODES * HID];   // z @ Wd
__device__ int   g_is64;

// ---------------- dtype detection for edge_index (int64 vs int32) --------
__global__ void detect_kernel(const void* ei) {
    int lane = threadIdx.x;
    const long long* p = (const long long*)ei;
    int ok = 1;
    for (int i = lane; i < 256; i += 32) {
        long long v = p[i];
        if (v < 0 || v >= N_NODES) ok = 0;
    }
    ok = __all_sync(0xffffffffu, ok);
    if (lane == 0) g_is64 = ok;
}

__device__ __forceinline__ int load_idx(const void* ei, long long i, int is64) {
    if (is64) return (int)((const long long*)ei)[i];
    return ((const int*)ei)[i];
}

// ---------------- CSR build ----------------
__global__ void zero_cnt_kernel() {
    int i = blockIdx.x * blockDim.x + threadIdx.x;
    if (i < N_NODES) g_cnt[i] = 0;
}

__global__ void hist_kernel(const void* __restrict__ ei) {
    int is64 = g_is64;
    int e = blockIdx.x * blockDim.x + threadIdx.x;
    if (e < N_EDGES) {
        int dst = load_idx(ei, (long long)N_EDGES + e, is64);
        atomicAdd(&g_cnt[dst], 1);
    }
}

// multi-block scan: stage 1 — block-local exclusive scan + block sums
__global__ void scan1_kernel() {
    __shared__ int s[1024];
    int t = threadIdx.x;
    int i = blockIdx.x * 1024 + t;
    int v = (i < N_NODES) ? g_cnt[i] : 0;
    s[t] = v;
    __syncthreads();
    for (int off = 1; off < 1024; off <<= 1) {
        int u = (t >= off) ? s[t - off] : 0;
        __syncthreads();
        s[t] += u;
        __syncthreads();
    }
    if (i < N_NODES) g_rowstart[i] = s[t] - v;   // exclusive within block
    if (t == 1023) g_bsum[blockIdx.x] = s[1023];
}

// stage 2 — scan the (<=128) block sums
__global__ void scan2_kernel(int nblocks) {
    __shared__ int s[128];
    int t = threadIdx.x;
    int v = (t < nblocks) ? g_bsum[t] : 0;
    s[t] = v;
    __syncthreads();
    for (int off = 1; off < 128; off <<= 1) {
        int u = (t >= off) ? s[t - off] : 0;
        __syncthreads();
        s[t] += u;
        __syncthreads();
    }
    g_boff[t] = s[t] - v;  // exclusive
}

// stage 3 — add block offsets, init cursor, close row pointer
__global__ void scan3_kernel() {
    int i = blockIdx.x * blockDim.x + threadIdx.x;
    if (i < N_NODES) {
        int r = g_rowstart[i] + g_boff[i >> 10];
        g_rowstart[i] = r;
        g_cursor[i] = r;
    }
    if (i == 0) g_rowstart[N_NODES] = N_EDGES;
}

__global__ void fill_kernel(const void* __restrict__ ei) {
    int is64 = g_is64;
    int e = blockIdx.x * blockDim.x + threadIdx.x;
    if (e < N_EDGES) {
        int dst = load_idx(ei, (long long)N_EDGES + e, is64);
        int src = load_idx(ei, (long long)e, is64);
        int p = atomicAdd(&g_cursor[dst], 1);
        g_esrc[p] = src;
    }
}

// ---------------- SAGE layer (mean-agg + dual GEMM + LN + ReLU) ----------
__global__ void __launch_bounds__(256) sage_kernel(
    const float* __restrict__ x0, int layer,
    const float* __restrict__ wl, const float* __restrict__ wr,
    const float* __restrict__ bias, const float* __restrict__ lng,
    const float* __restrict__ lnb)
{
    __shared__ float wl_s[64 * 64], wr_s[64 * 64];
    __shared__ float mean_s[8][64], x_s[8][64];
    __shared__ float b_s[64], g_s[64], bb_s[64];

    const float* xin = (layer == 0) ? x0 : g_h;
    float* xout = (layer == 0) ? g_h : g_z;

    int tid = threadIdx.x;
    for (int i = tid; i < 64 * 64; i += 256) { wl_s[i] = wl[i]; wr_s[i] = wr[i]; }
    if (tid < 64) { b_s[tid] = bias[tid]; g_s[tid] = lng[tid]; bb_s[tid] = lnb[tid]; }
    __syncthreads();

    int w = tid >> 5, lane = tid & 31;

    for (int base = blockIdx.x * 8; base < N_NODES; base += gridDim.x * 8) {
        int node = base + w;
        if (node < N_NODES) {
            int rs = g_rowstart[node], re = g_rowstart[node + 1];
            float a0 = 0.f, a1 = 0.f;
            for (int i = rs; i < re; i++) {
                int src = g_esrc[i];
                const float* xp = xin + (size_t)src * 64;
                a0 += xp[lane];
                a1 += xp[lane + 32];
            }
            float inv = 1.f / (float)max(re - rs, 1);
            const float* xn = xin + (size_t)node * 64;
            mean_s[w][lane]      = a0 * inv;
            mean_s[w][lane + 32] = a1 * inv;
            x_s[w][lane]      = xn[lane];
            x_s[w][lane + 32] = xn[lane + 32];
        }
        __syncwarp();
        if (node < N_NODES) {
            float o0 = b_s[lane], o1 = b_s[lane + 32];
            #pragma unroll 8
            for (int k = 0; k < 64; k++) {
                float m = mean_s[w][k], xv = x_s[w][k];
                o0 += m * wl_s[k * 64 + lane]      + xv * wr_s[k * 64 + lane];
                o1 += m * wl_s[k * 64 + lane + 32] + xv * wr_s[k * 64 + lane + 32];
            }
            float ssum = o0 + o1;
            #pragma unroll
            for (int off = 16; off > 0; off >>= 1) ssum += __shfl_xor_sync(0xffffffffu, ssum, off);
            float mu = ssum * (1.f / 64.f);
            float d0 = o0 - mu, d1 = o1 - mu;
            float vsum = d0 * d0 + d1 * d1;
            #pragma unroll
            for (int off = 16; off > 0; off >>= 1) vsum += __shfl_xor_sync(0xffffffffu, vsum, off);
            float rstd = rsqrtf(vsum * (1.f / 64.f) + 1e-5f);
            float r0 = d0 * rstd * g_s[lane]      + bb_s[lane];
            float r1 = d1 * rstd * g_s[lane + 32] + bb_s[lane + 32];
            xout[(size_t)node * 64 + lane]      = fmaxf(r0, 0.f);
            xout[(size_t)node * 64 + lane + 32] = fmaxf(r1, 0.f);
        }
        __syncwarp();
    }
}

// ---------------- per-node precompute: A = z@Ws + cb1, B = z@Wd ----------
// Ws = cw1 rows [0,64), Wd = cw1 rows [64,128)
__global__ void __launch_bounds__(256) node_pre_kernel(
    const float* __restrict__ cw1, const float* __restrict__ cb1)
{
    __shared__ float ws_s[64 * 64], wd_s[64 * 64];
    __shared__ float z_s[8][64];
    __shared__ float cb_s[64];

    int tid = threadIdx.x;
    for (int i = tid; i < 64 * 64; i += 256) {
        ws_s[i] = cw1[i];
        wd_s[i] = cw1[64 * 64 + i];
    }
    if (tid < 64) cb_s[tid] = cb1[tid];
    __syncthreads();

    int w = tid >> 5, lane = tid & 31;

    for (int base = blockIdx.x * 8; base < N_NODES; base += gridDim.x * 8) {
        int node = base + w;
        if (node < N_NODES) {
            const float* zp = g_z + (size_t)node * 64;
            z_s[w][lane]      = zp[lane];
            z_s[w][lane + 32] = zp[lane + 32];
        }
        __syncwarp();
        if (node < N_NODES) {
            float a0 = cb_s[lane], a1 = cb_s[lane + 32];
            float b0 = 0.f, b1 = 0.f;
            #pragma unroll 8
            for (int k = 0; k < 64; k++) {
                float zv = z_s[w][k];
                a0 += zv * ws_s[k * 64 + lane];
                a1 += zv * ws_s[k * 64 + lane + 32];
                b0 += zv * wd_s[k * 64 + lane];
                b1 += zv * wd_s[k * 64 + lane + 32];
            }
            g_A[(size_t)node * 64 + lane]      = a0;
            g_A[(size_t)node * 64 + lane + 32] = a1;
            g_B[(size_t)node * 64 + lane]      = b0;
            g_B[(size_t)node * 64 + lane + 32] = b1;
        }
        __syncwarp();
    }
}

// ---------------- Edge classifier MLP (factored) --------------------------
// h1 = relu(A[src] + B[dst] + (z_s*z_d)@Wp + ea@We)
// Wp = cw1 rows [128,192), We = cw1 rows [192,224)
#define ETILE 8
#define WPT_STRIDE 68   // 64 k + pad (272B rows -> conflict-free)
#define WET_STRIDE 36   // 32 j + pad (144B rows)
#define CW2T_STRIDE 68
#define REPR_STRIDE 100 // p[64] + ea[32] + pad

// dynamic smem layout (floats):
//   wp_t : 64*68  = 4352   [0, 4352)
//   we_t : 64*36  = 2304   [4352, 6656)
//   cw2t : 32*68  = 2176   [6656, 8832)
//   cb2s : 32              [8832, 8864)
//   cw3s : 32              [8864, 8896)
//   repr : 8w*8e*100 = 6400 [8896, 15296)
//   h1s  : 8w*8e*64  = 4096 [15296, 19392)
#define EDGE_SMEM_FLOATS 19392
#define EDGE_SMEM_BYTES (EDGE_SMEM_FLOATS * 4)

extern __shared__ float sm_edge[];

__global__ void __launch_bounds__(256) edge_mlp_kernel(
    const void* __restrict__ ei, const float* __restrict__ ea,
    const float* __restrict__ cw1,
    const float* __restrict__ cw2, const float* __restrict__ cb2,
    const float* __restrict__ cw3, const float* __restrict__ cb3,
    float* __restrict__ out)
{
    float* wp_t = sm_edge;
    float* we_t = wp_t + 64 * WPT_STRIDE;
    float* cw2t = we_t + 64 * WET_STRIDE;
    float* cb2s = cw2t + 32 * CW2T_STRIDE;
    float* cw3s = cb2s + 32;
    float* reprs = cw3s + 32;
    float* h1s   = reprs + 8 * ETILE * REPR_STRIDE;

    int tid = threadIdx.x;
    // wp_t[f][k] = cw1[(128+k)*64 + f]
    for (int i = tid; i < 64 * 64; i += 256) {
        int k = i >> 6, f = i & 63;
        wp_t[f * WPT_STRIDE + k] = cw1[(128 + k) * 64 + f];
    }
    // we_t[f][j] = cw1[(192+j)*64 + f]
    for (int i = tid; i < 32 * 64; i += 256) {
        int j = i >> 6, f = i & 63;
        we_t[f * WET_STRIDE + j] = cw1[(192 + j) * 64 + f];
    }
    // cw2t[j][f] = cw2[f*32 + j]
    for (int i = tid; i < 64 * 32; i += 256) {
        int f = i >> 5, j = i & 31;
        cw2t[j * CW2T_STRIDE + f] = cw2[i];
    }
    if (tid < 32) { cb2s[tid] = cb2[tid]; cw3s[tid] = cw3[tid]; }
    __syncthreads();

    const int is64 = g_is64;
    const float cb3v = cb3[0];
    int w = tid >> 5, lane = tid & 31;
    float* myrepr = reprs + w * (ETILE * REPR_STRIDE);
    float* myh1 = h1s + w * (ETILE * 64);

    // N_EDGES is a multiple of 64 (blockDim covers 64 edges/iter) -> no tail
    for (int blockbase = blockIdx.x * 64; blockbase < N_EDGES; blockbase += gridDim.x * 64) {
        int e0 = blockbase + w * ETILE;

        // ---- gather: p = z_s*z_d, ea into smem; A[src]+B[dst] init into h1s
        #pragma unroll
        for (int t = 0; t < ETILE; t++) {
            int e = e0 + t;
            int src = load_idx(ei, (long long)e, is64);
            int dst = load_idx(ei, (long long)N_EDGES + e, is64);
            float* rp = myrepr + t * REPR_STRIDE;
            float2 a = ((const float2*)(g_z + (size_t)src * 64))[lane];
            float2 b = ((const float2*)(g_z + (size_t)dst * 64))[lane];
            float2 p; p.x = a.x * b.x; p.y = a.y * b.y;
            ((float2*)rp)[lane] = p;
            if (lane < 16)
                ((float2*)(rp + 64))[lane] = ((const float2*)(ea + (size_t)e * 32))[lane];
            float2 av = ((const float2*)(g_A + (size_t)src * 64))[lane];
            float2 bv = ((const float2*)(g_B + (size_t)dst * 64))[lane];
            float2 s; s.x = av.x + bv.x; s.y = av.y + bv.y;
            ((float2*)(myh1 + t * 64))[lane] = s;
        }
        __syncwarp();

        // ---- h1 += p@Wp + ea@We ; lane owns features (lane, lane+32) ----
        float acc[ETILE][2];
        #pragma unroll
        for (int t = 0; t < ETILE; t++) {
            acc[t][0] = myh1[t * 64 + lane];
            acc[t][1] = myh1[t * 64 + lane + 32];
        }
        {
            const float4* w0 = (const float4*)(wp_t + lane * WPT_STRIDE);
            const float4* w1 = (const float4*)(wp_t + (lane + 32) * WPT_STRIDE);
            #pragma unroll 4
            for (int k4 = 0; k4 < 16; k4++) {
                float4 u = w0[k4], v = w1[k4];
                #pragma unroll
                for (int t = 0; t < ETILE; t++) {
                    float4 r = ((const float4*)(myrepr + t * REPR_STRIDE))[k4];
                    acc[t][0] += r.x * u.x + r.y * u.y + r.z * u.z + r.w * u.w;
                    acc[t][1] += r.x * v.x + r.y * v.y + r.z * v.z + r.w * v.w;
                }
            }
        }
        {
            const float4* w0 = (const float4*)(we_t + lane * WET_STRIDE);
            const float4* w1 = (const float4*)(we_t + (lane + 32) * WET_STRIDE);
            #pragma unroll 4
            for (int j4 = 0; j4 < 8; j4++) {
                float4 u = w0[j4], v = w1[j4];
                #pragma unroll
                for (int t = 0; t < ETILE; t++) {
                    float4 r = ((const float4*)(myrepr + 64 + t * REPR_STRIDE))[j4];
                    acc[t][0] += r.x * u.x + r.y * u.y + r.z * u.z + r.w * u.w;
                    acc[t][1] += r.x * v.x + r.y * v.y + r.z * v.z + r.w * v.w;
                }
            }
        }
        __syncwarp();
        #pragma unroll
        for (int t = 0; t < ETILE; t++) {
            myh1[t * 64 + lane]      = fmaxf(acc[t][0], 0.f);
            myh1[t * 64 + lane + 32] = fmaxf(acc[t][1], 0.f);
        }
        __syncwarp();

        // ---- h2 = relu(h1 @ cw2 + cb2) ; lane owns output j ----
        float acc2[ETILE];
        #pragma unroll
        for (int t = 0; t < ETILE; t++) acc2[t] = cb2s[lane];
        {
            const float4* w2 = (const float4*)(cw2t + lane * CW2T_STRIDE);
            #pragma unroll 4
            for (int f4 = 0; f4 < 16; f4++) {
                float4 u = w2[f4];
                #pragma unroll
                for (int t = 0; t < ETILE; t++) {
                    float4 h = ((const float4*)(myh1 + t * 64))[f4];
                    acc2[t] += h.x * u.x + h.y * u.y + h.z * u.z + h.w * u.w;
                }
            }
        }
        // ---- logit = relu(h2) @ cw3 + cb3 ----
        #pragma unroll
        for (int t = 0; t < ETILE; t++) {
            float part = fmaxf(acc2[t], 0.f) * cw3s[lane];
            #pragma unroll
            for (int off = 16; off > 0; off >>= 1)
                part += __shfl_xor_sync(0xffffffffu, part, off);
            if (lane == 0) out[e0 + t] = part + cb3v;
        }
        __syncwarp();
    }
}

// ---------------- launch ----------------
extern "C" void kernel_launch(void* const* d_in, const int* in_sizes, int n_in,
                              void* d_out, int out_size)
{
    const float* x   = (const float*)d_in[0];
    const void*  ei  = (const void*)d_in[1];
    const float* ea  = (const float*)d_in[2];
    const float* wl0 = (const float*)d_in[3];
    const float* wr0 = (const float*)d_in[4];
    const float* b0  = (const float*)d_in[5];
    const float* g0  = (const float*)d_in[6];
    const float* bb0 = (const float*)d_in[7];
    const float* wl1 = (const float*)d_in[8];
    const float* wr1 = (const float*)d_in[9];
    const float* b1  = (const float*)d_in[10];
    const float* g1  = (const float*)d_in[11];
    const float* bb1 = (const float*)d_in[12];
    const float* cw1 = (const float*)d_in[13];
    const float* cb1 = (const float*)d_in[14];
    const float* cw2 = (const float*)d_in[15];
    const float* cb2 = (const float*)d_in[16];
    const float* cw3 = (const float*)d_in[17];
    const float* cb3 = (const float*)d_in[18];
    float* out = (float*)d_out;

    const int GRID_SAGE = 888;
    const int GRID_EDGE = 296;   // 2 blocks/SM (smem-limited)
    const int SCAN_BLOCKS = (N_NODES + 1023) / 1024;  // 98

    detect_kernel<<<1, 32>>>(ei);
    zero_cnt_kernel<<<(N_NODES + 255) / 256, 256>>>();
    hist_kernel<<<(N_EDGES + 255) / 256, 256>>>(ei);
    scan1_kernel<<<SCAN_BLOCKS, 1024>>>();
    scan2_kernel<<<1, 128>>>(SCAN_BLOCKS);
    scan3_kernel<<<(N_NODES + 255) / 256, 256>>>();
    fill_kernel<<<(N_EDGES + 255) / 256, 256>>>(ei);

    sage_kernel<<<GRID_SAGE, 256>>>(x, 0, wl0, wr0, b0, g0, bb0);
    sage_kernel<<<GRID_SAGE, 256>>>(x, 1, wl1, wr1, b1, g1, bb1);
    node_pre_kernel<<<GRID_SAGE, 256>>>(cw1, cb1);

    cudaFuncSetAttribute(edge_mlp_kernel,
                         cudaFuncAttributeMaxDynamicSharedMemorySize, EDGE_SMEM_BYTES);
    edge_mlp_kernel<<<GRID_EDGE, 256, EDGE_SMEM_BYTES>>>(
        ei, ea, cw1, cw2, cb2, cw3, cb3, out);
}

// round 4
// speedup vs baseline: 1.9436x; 1.0699x over previous
#include <cuda_runtime.h>
#include <cuda_bf16.h>
#include <cstdint>

#define N_NODES 100000
#define N_EDGES 1200000
#define HID 64

// ---------------- device scratch (no allocations allowed) ----------------
__device__ int   g_cnt[N_NODES];
__device__ int   g_rowstart[N_NODES + 1];
__device__ int   g_cursor[N_NODES];
__device__ int   g_bsum[128];
__device__ int   g_boff[128];
__device__ int   g_esrc[N_EDGES];
__device__ float g_h[(size_t)N_NODES * HID];
__device__ float g_z[(size_t)N_NODES * HID];
__device__ float g_A[(size_t)N_NODES * HID];   // z @ Ws + cb1
__device__ float g_B[(size_t)N_NODES * HID];   // z @ Wd
__device__ int   g_is64;

// ---------------- helpers -------------------------------------------------
__device__ __forceinline__ void bf16_split(float v, float& hi, float& lo) {
    __nv_bfloat16 h = __float2bfloat16(v);
    hi = __bfloat162float(h);
    lo = v - hi;
}
__device__ __forceinline__ uint32_t pack2(float a, float b) {
    __nv_bfloat162 h = __floats2bfloat162_rn(a, b);
    return *(uint32_t*)&h;
}
// mma.sync m16n8k16 bf16 (A row-major frag, B col-major frag), f32 accum
__device__ __forceinline__ void hmma(float* d, const uint4 a, const uint2 b) {
    asm volatile("mma.sync.aligned.m16n8k16.row.col.f32.bf16.bf16.f32 "
        "{%0,%1,%2,%3}, {%4,%5,%6,%7}, {%8,%9}, {%0,%1,%2,%3};"
        : "+f"(d[0]), "+f"(d[1]), "+f"(d[2]), "+f"(d[3])
        : "r"(a.x), "r"(a.y), "r"(a.z), "r"(a.w), "r"(b.x), "r"(b.y));
}

// ---------------- dtype detection for edge_index (int64 vs int32) --------
__global__ void detect_kernel(const void* ei) {
    int lane = threadIdx.x;
    const long long* p = (const long long*)ei;
    int ok = 1;
    for (int i = lane; i < 256; i += 32) {
        long long v = p[i];
        if (v < 0 || v >= N_NODES) ok = 0;
    }
    ok = __all_sync(0xffffffffu, ok);
    if (lane == 0) g_is64 = ok;
}

__device__ __forceinline__ int load_idx(const void* ei, long long i, int is64) {
    if (is64) return (int)((const long long*)ei)[i];
    return ((const int*)ei)[i];
}

// ---------------- CSR build ----------------
__global__ void zero_cnt_kernel() {
    int i = blockIdx.x * blockDim.x + threadIdx.x;
    if (i < N_NODES) g_cnt[i] = 0;
}

__global__ void hist_kernel(const void* __restrict__ ei) {
    int is64 = g_is64;
    int e = blockIdx.x * blockDim.x + threadIdx.x;
    if (e < N_EDGES) {
        int dst = load_idx(ei, (long long)N_EDGES + e, is64);
        atomicAdd(&g_cnt[dst], 1);
    }
}

__global__ void scan1_kernel() {
    __shared__ int s[1024];
    int t = threadIdx.x;
    int i = blockIdx.x * 1024 + t;
    int v = (i < N_NODES) ? g_cnt[i] : 0;
    s[t] = v;
    __syncthreads();
    for (int off = 1; off < 1024; off <<= 1) {
        int u = (t >= off) ? s[t - off] : 0;
        __syncthreads();
        s[t] += u;
        __syncthreads();
    }
    if (i < N_NODES) g_rowstart[i] = s[t] - v;
    if (t == 1023) g_bsum[blockIdx.x] = s[1023];
}

__global__ void scan2_kernel(int nblocks) {
    __shared__ int s[128];
    int t = threadIdx.x;
    int v = (t < nblocks) ? g_bsum[t] : 0;
    s[t] = v;
    __syncthreads();
    for (int off = 1; off < 128; off <<= 1) {
        int u = (t >= off) ? s[t - off] : 0;
        __syncthreads();
        s[t] += u;
        __syncthreads();
    }
    g_boff[t] = s[t] - v;
}

__global__ void scan3_kernel() {
    int i = blockIdx.x * blockDim.x + threadIdx.x;
    if (i < N_NODES) {
        int r = g_rowstart[i] + g_boff[i >> 10];
        g_rowstart[i] = r;
        g_cursor[i] = r;
    }
    if (i == 0) g_rowstart[N_NODES] = N_EDGES;
}

__global__ void fill_kernel(const void* __restrict__ ei) {
    int is64 = g_is64;
    int e = blockIdx.x * blockDim.x + threadIdx.x;
    if (e < N_EDGES) {
        int dst = load_idx(ei, (long long)N_EDGES + e, is64);
        int src = load_idx(ei, (long long)e, is64);
        int p = atomicAdd(&g_cursor[dst], 1);
        g_esrc[p] = src;
    }
}

// ---------------- SAGE layer (mean-agg + dual GEMM + LN + ReLU) ----------
__global__ void __launch_bounds__(256) sage_kernel(
    const float* __restrict__ x0, int layer,
    const float* __restrict__ wl, const float* __restrict__ wr,
    const float* __restrict__ bias, const float* __restrict__ lng,
    const float* __restrict__ lnb)
{
    __shared__ float wl_s[64 * 64], wr_s[64 * 64];
    __shared__ float mean_s[8][64], x_s[8][64];
    __shared__ float b_s[64], g_s[64], bb_s[64];

    const float* xin = (layer == 0) ? x0 : g_h;
    float* xout = (layer == 0) ? g_h : g_z;

    int tid = threadIdx.x;
    for (int i = tid; i < 64 * 64; i += 256) { wl_s[i] = wl[i]; wr_s[i] = wr[i]; }
    if (tid < 64) { b_s[tid] = bias[tid]; g_s[tid] = lng[tid]; bb_s[tid] = lnb[tid]; }
    __syncthreads();

    int w = tid >> 5, lane = tid & 31;

    for (int base = blockIdx.x * 8; base < N_NODES; base += gridDim.x * 8) {
        int node = base + w;
        if (node < N_NODES) {
            int rs = g_rowstart[node], re = g_rowstart[node + 1];
            float a0 = 0.f, a1 = 0.f;
            for (int i = rs; i < re; i++) {
                int src = g_esrc[i];
                const float* xp = xin + (size_t)src * 64;
                a0 += xp[lane];
                a1 += xp[lane + 32];
            }
            float inv = 1.f / (float)max(re - rs, 1);
            const float* xn = xin + (size_t)node * 64;
            mean_s[w][lane]      = a0 * inv;
            mean_s[w][lane + 32] = a1 * inv;
            x_s[w][lane]      = xn[lane];
            x_s[w][lane + 32] = xn[lane + 32];
        }
        __syncwarp();
        if (node < N_NODES) {
            float o0 = b_s[lane], o1 = b_s[lane + 32];
            #pragma unroll 8
            for (int k = 0; k < 64; k++) {
                float m = mean_s[w][k], xv = x_s[w][k];
                o0 += m * wl_s[k * 64 + lane]      + xv * wr_s[k * 64 + lane];
                o1 += m * wl_s[k * 64 + lane + 32] + xv * wr_s[k * 64 + lane + 32];
            }
            float ssum = o0 + o1;
            #pragma unroll
            for (int off = 16; off > 0; off >>= 1) ssum += __shfl_xor_sync(0xffffffffu, ssum, off);
            float mu = ssum * (1.f / 64.f);
            float d0 = o0 - mu, d1 = o1 - mu;
            float vsum = d0 * d0 + d1 * d1;
            #pragma unroll
            for (int off = 16; off > 0; off >>= 1) vsum += __shfl_xor_sync(0xffffffffu, vsum, off);
            float rstd = rsqrtf(vsum * (1.f / 64.f) + 1e-5f);
            float r0 = d0 * rstd * g_s[lane]      + bb_s[lane];
            float r1 = d1 * rstd * g_s[lane + 32] + bb_s[lane + 32];
            xout[(size_t)node * 64 + lane]      = fmaxf(r0, 0.f);
            xout[(size_t)node * 64 + lane + 32] = fmaxf(r1, 0.f);
        }
        __syncwarp();
    }
}

// ---------------- per-node precompute: A = z@Ws + cb1, B = z@Wd ----------
__global__ void __launch_bounds__(256) node_pre_kernel(
    const float* __restrict__ cw1, const float* __restrict__ cb1)
{
    __shared__ float ws_s[64 * 64], wd_s[64 * 64];
    __shared__ float z_s[8][64];
    __shared__ float cb_s[64];

    int tid = threadIdx.x;
    for (int i = tid; i < 64 * 64; i += 256) {
        ws_s[i] = cw1[i];
        wd_s[i] = cw1[64 * 64 + i];
    }
    if (tid < 64) cb_s[tid] = cb1[tid];
    __syncthreads();

    int w = tid >> 5, lane = tid & 31;

    for (int base = blockIdx.x * 8; base < N_NODES; base += gridDim.x * 8) {
        int node = base + w;
        if (node < N_NODES) {
            const float* zp = g_z + (size_t)node * 64;
            z_s[w][lane]      = zp[lane];
            z_s[w][lane + 32] = zp[lane + 32];
        }
        __syncwarp();
        if (node < N_NODES) {
            float a0 = cb_s[lane], a1 = cb_s[lane + 32];
            float b0 = 0.f, b1 = 0.f;
            #pragma unroll 8
            for (int k = 0; k < 64; k++) {
                float zv = z_s[w][k];
                a0 += zv * ws_s[k * 64 + lane];
                a1 += zv * ws_s[k * 64 + lane + 32];
                b0 += zv * wd_s[k * 64 + lane];
                b1 += zv * wd_s[k * 64 + lane + 32];
            }
            g_A[(size_t)node * 64 + lane]      = a0;
            g_A[(size_t)node * 64 + lane + 32] = a1;
            g_B[(size_t)node * 64 + lane]      = b0;
            g_B[(size_t)node * 64 + lane + 32] = b1;
        }
        __syncwarp();
    }
}

// ================= Edge classifier via mma.sync bf16-split ================
// L1: h1 = relu(base + [p|ea] @ W1), p = z_s*z_d (64), ea (32) -> K0=96.
//     bf16 2-term split, 3 logical passes folded into 18 k16-steps:
//       s 0..5  : A=hi  x Whi      s 6..11 : A=lo x Whi     s 12..17: A=hi x Wlo
// L2: h2 = relu(h1 @ W2 + cb2), 12 k16-steps (hi/lo/hi x Whi/Whi/Wlo),
//     logit = relu(h2) . cw3 + cb3.
// All MMA operands live in SMEM in *pre-fragmented* layout: each lane's
// m16n8k16 fragment regs are contiguous (LDS.128 for A, LDS.64 for B).

#define M_TILE 128
#define N_TILES (N_EDGES / M_TILE)   // 9375

// smem byte offsets
#define OFF_A1   0                     // 8 rowgrp x 12 kstep x 512B = 49152
#define OFF_A2   49152                 // 8 x 8 x 512               = 32768
#define OFF_B1   81920                 // 8 ntile x 18 kstep x 256B = 36864
#define OFF_B2   118784                // 4 x 12 x 256              = 12288
#define OFF_BASE 131072                // 128 x 68 f32              = 34816
#define OFF_LOG  165888                // 128 f32                   = 512
#define OFF_CB2  166400                // 32 f32 (pad to 128)
#define OFF_CW3  166528                // 32 f32 (pad to 128)
#define EDGE_SMEM_TOTAL 166656

// fragment addressing: region(rowgrp, kstep) 512B; lane slot 16B; reg 4B
__device__ __forceinline__ uint32_t a1_off(int r, int c2) {
    return (uint32_t)(((r >> 4) * 12 + (c2 >> 3)) << 9)
         + (((r & 7) * 4 + (c2 & 3)) << 4)
         + ((((r >> 3) & 1) + 2 * ((c2 >> 2) & 1)) << 2);
}
__device__ __forceinline__ uint32_t a2_off(int r, int c2) {
    return (uint32_t)(((r >> 4) * 8 + (c2 >> 3)) << 9)
         + (((r & 7) * 4 + (c2 & 3)) << 4)
         + ((((r >> 3) & 1) + 2 * ((c2 >> 2) & 1)) << 2);
}

__global__ void __launch_bounds__(512, 1) edge_mma_kernel(
    const void* __restrict__ ei, const float* __restrict__ ea,
    const float* __restrict__ cw1,
    const float* __restrict__ cw2, const float* __restrict__ cb2,
    const float* __restrict__ cw3, const float* __restrict__ cb3,
    float* __restrict__ out)
{
    extern __shared__ char smem[];
    float* base_s = (float*)(smem + OFF_BASE);
    float* log_s  = (float*)(smem + OFF_LOG);
    float* cb2s   = (float*)(smem + OFF_CB2);
    float* cw3s   = (float*)(smem + OFF_CW3);

    const int tid = threadIdx.x;
    const int wid = tid >> 5, lane = tid & 31;
    const int q = lane & 3;

    // ---- weight prologue: pre-fragmented B1/B2 -----------------------------
    // B1 regions (nt 0..7, ks 0..17); per lane 2 regs; k = 16*ks + 2*(lane&3) + 8*reg
    for (int i = tid; i < 8 * 18 * 64; i += 512) {
        int nt = i / (18 * 64);
        int rem = i % (18 * 64);
        int ks = rem >> 6;
        int j = rem & 63;
        int ln = j >> 1, rg = j & 1;
        int n = nt * 8 + (ln >> 2);
        int k = ks * 16 + 2 * (ln & 3) + 8 * rg;
        int sec = k / 96, kr = k % 96;
        float w0 = cw1[(128 + kr) * 64 + n];
        float w1 = cw1[(128 + kr + 1) * 64 + n];
        float h0, l0, h1, l1;
        bf16_split(w0, h0, l0); bf16_split(w1, h1, l1);
        uint32_t v = (sec < 2) ? pack2(h0, h1) : pack2(l0, l1);
        *(uint32_t*)(smem + OFF_B1 + ((nt * 18 + ks) << 8) + ln * 8 + rg * 4) = v;
    }
    // B2 regions (nt 0..3, ks 0..11); k = 16*ks + ... in [0,192)
    for (int i = tid; i < 4 * 12 * 64; i += 512) {
        int nt = i / (12 * 64);
        int rem = i % (12 * 64);
        int ks = rem >> 6;
        int j = rem & 63;
        int ln = j >> 1, rg = j & 1;
        int n = nt * 8 + (ln >> 2);
        int k = ks * 16 + 2 * (ln & 3) + 8 * rg;
        int sec = k / 64, kr = k % 64;
        float w0 = cw2[kr * 32 + n];
        float w1 = cw2[(kr + 1) * 32 + n];
        float h0, l0, h1, l1;
        bf16_split(w0, h0, l0); bf16_split(w1, h1, l1);
        uint32_t v = (sec < 2) ? pack2(h0, h1) : pack2(l0, l1);
        *(uint32_t*)(smem + OFF_B2 + ((nt * 12 + ks) << 8) + ln * 8 + rg * 4) = v;
    }
    if (tid < 32) { cb2s[tid] = cb2[tid]; cw3s[tid] = cw3[tid]; }
    if (tid < 128) log_s[tid] = 0.f;
    __syncthreads();

    const int is64 = g_is64;
    const float cb3v = cb3[0];
    const int rowgrp = wid & 7, nhalf = wid >> 3;

    for (int tile = blockIdx.x; tile < N_TILES; tile += gridDim.x) {
        const int e0 = tile * M_TILE;

        // ---------------- gather: 16 warps x 8 edges ----------------
        #pragma unroll 2
        for (int t = 0; t < 8; t++) {
            int r = wid * 8 + t;
            int e = e0 + r;
            int src = load_idx(ei, (long long)e, is64);
            int dst = load_idx(ei, (long long)N_EDGES + e, is64);
            float2 a = ((const float2*)(g_z + (size_t)src * 64))[lane];
            float2 b = ((const float2*)(g_z + (size_t)dst * 64))[lane];
            float px = a.x * b.x, py = a.y * b.y;
            float hx, lx, hy, ly;
            bf16_split(px, hx, lx); bf16_split(py, hy, ly);
            *(uint32_t*)(smem + OFF_A1 + a1_off(r, lane))      = pack2(hx, hy);
            *(uint32_t*)(smem + OFF_A1 + a1_off(r, lane + 48)) = pack2(lx, ly);
            if (lane < 16) {
                float2 e2 = ((const float2*)(ea + (size_t)e * 32))[lane];
                float eh0, el0, eh1, el1;
                bf16_split(e2.x, eh0, el0); bf16_split(e2.y, eh1, el1);
                *(uint32_t*)(smem + OFF_A1 + a1_off(r, 32 + lane)) = pack2(eh0, eh1);
                *(uint32_t*)(smem + OFF_A1 + a1_off(r, 80 + lane)) = pack2(el0, el1);
            }
            float2 av = ((const float2*)(g_A + (size_t)src * 64))[lane];
            float2 bv = ((const float2*)(g_B + (size_t)dst * 64))[lane];
            base_s[r * 68 + 2 * lane]     = av.x + bv.x;
            base_s[r * 68 + 2 * lane + 1] = av.y + bv.y;
        }
        __syncthreads();

        // ---------------- L1 GEMM: 16 rows x 32 cols per warp ----------------
        float d[4][4] = {};
        #pragma unroll
        for (int s = 0; s < 18; s++) {
            int aks = (s < 12) ? s : s - 12;
            uint4 A = *(const uint4*)(smem + OFF_A1 + ((rowgrp * 12 + aks) << 9) + lane * 16);
            #pragma unroll
            for (int nt = 0; nt < 4; nt++) {
                int ntg = nhalf * 4 + nt;
                uint2 B = *(const uint2*)(smem + OFF_B1 + ((ntg * 18 + s) << 8) + lane * 8);
                hmma(d[nt], A, B);
            }
        }

        // ---------------- epilogue 1: +base, relu, split -> A2 fragments ----
        {
            int r0 = rowgrp * 16 + (lane >> 2);
            #pragma unroll
            for (int nt = 0; nt < 4; nt++) {
                int c0 = nhalf * 32 + nt * 8 + 2 * q;
                float v00 = fmaxf(d[nt][0] + base_s[r0 * 68 + c0], 0.f);
                float v01 = fmaxf(d[nt][1] + base_s[r0 * 68 + c0 + 1], 0.f);
                float v10 = fmaxf(d[nt][2] + base_s[(r0 + 8) * 68 + c0], 0.f);
                float v11 = fmaxf(d[nt][3] + base_s[(r0 + 8) * 68 + c0 + 1], 0.f);
                float h00, l00, h01, l01, h10, l10, h11, l11;
                bf16_split(v00, h00, l00); bf16_split(v01, h01, l01);
                bf16_split(v10, h10, l10); bf16_split(v11, h11, l11);
                int c2 = c0 >> 1;
                *(uint32_t*)(smem + OFF_A2 + a2_off(r0,     c2))      = pack2(h00, h01);
                *(uint32_t*)(smem + OFF_A2 + a2_off(r0 + 8, c2))      = pack2(h10, h11);
                *(uint32_t*)(smem + OFF_A2 + a2_off(r0,     c2 + 32)) = pack2(l00, l01);
                *(uint32_t*)(smem + OFF_A2 + a2_off(r0 + 8, c2 + 32)) = pack2(l10, l11);
            }
        }
        __syncthreads();

        // ---------------- L2 GEMM: 16 rows x 16 cols per warp ----------------
        float e2a[2][4] = {};
        #pragma unroll
        for (int s = 0; s < 12; s++) {
            int aks = (s < 8) ? s : s - 8;
            uint4 A = *(const uint4*)(smem + OFF_A2 + ((rowgrp * 8 + aks) << 9) + lane * 16);
            #pragma unroll
            for (int nt = 0; nt < 2; nt++) {
                int ntg = nhalf * 2 + nt;
                uint2 B = *(const uint2*)(smem + OFF_B2 + ((ntg * 12 + s) << 8) + lane * 8);
                hmma(e2a[nt], A, B);
            }
        }

        // ---------------- epilogue 2: +cb2, relu, dot cw3, reduce ------------
        {
            float p0 = 0.f, p1 = 0.f;
            #pragma unroll
            for (int nt = 0; nt < 2; nt++) {
                int c0 = nhalf * 16 + nt * 8 + 2 * q;
                float w0 = cw3s[c0], w1 = cw3s[c0 + 1];
                float b0 = cb2s[c0], b1 = cb2s[c0 + 1];
                p0 += fmaxf(e2a[nt][0] + b0, 0.f) * w0 + fmaxf(e2a[nt][1] + b1, 0.f) * w1;
                p1 += fmaxf(e2a[nt][2] + b0, 0.f) * w0 + fmaxf(e2a[nt][3] + b1, 0.f) * w1;
            }
            p0 += __shfl_xor_sync(0xffffffffu, p0, 1);
            p0 += __shfl_xor_sync(0xffffffffu, p0, 2);
            p1 += __shfl_xor_sync(0xffffffffu, p1, 1);
            p1 += __shfl_xor_sync(0xffffffffu, p1, 2);
            if (q == 0) {
                int r0 = rowgrp * 16 + (lane >> 2);
                atomicAdd(&log_s[r0], p0);
                atomicAdd(&log_s[r0 + 8], p1);
            }
        }
        __syncthreads();

        if (tid < 128) {
            out[e0 + tid] = log_s[tid] + cb3v;
            log_s[tid] = 0.f;
        }
        // next gather writes A1/base only; logits reset by same threads that read
    }
}

// ---------------- launch ----------------
extern "C" void kernel_launch(void* const* d_in, const int* in_sizes, int n_in,
                              void* d_out, int out_size)
{
    const float* x   = (const float*)d_in[0];
    const void*  ei  = (const void*)d_in[1];
    const float* ea  = (const float*)d_in[2];
    const float* wl0 = (const float*)d_in[3];
    const float* wr0 = (const float*)d_in[4];
    const float* b0  = (const float*)d_in[5];
    const float* g0  = (const float*)d_in[6];
    const float* bb0 = (const float*)d_in[7];
    const float* wl1 = (const float*)d_in[8];
    const float* wr1 = (const float*)d_in[9];
    const float* b1  = (const float*)d_in[10];
    const float* g1  = (const float*)d_in[11];
    const float* bb1 = (const float*)d_in[12];
    const float* cw1 = (const float*)d_in[13];
    const float* cb1 = (const float*)d_in[14];
    const float* cw2 = (const float*)d_in[15];
    const float* cb2 = (const float*)d_in[16];
    const float* cw3 = (const float*)d_in[17];
    const float* cb3 = (const float*)d_in[18];
    float* out = (float*)d_out;

    const int GRID_SAGE = 912;
    const int SCAN_BLOCKS = (N_NODES + 1023) / 1024;  // 98

    detect_kernel<<<1, 32>>>(ei);
    zero_cnt_kernel<<<(N_NODES + 255) / 256, 256>>>();
    hist_kernel<<<(N_EDGES + 255) / 256, 256>>>(ei);
    scan1_kernel<<<SCAN_BLOCKS, 1024>>>();
    scan2_kernel<<<1, 128>>>(SCAN_BLOCKS);
    scan3_kernel<<<(N_NODES + 255) / 256, 256>>>();
    fill_kernel<<<(N_EDGES + 255) / 256, 256>>>(ei);

    sage_kernel<<<GRID_SAGE, 256>>>(x, 0, wl0, wr0, b0, g0, bb0);
    sage_kernel<<<GRID_SAGE, 256>>>(x, 1, wl1, wr1, b1, g1, bb1);
    node_pre_kernel<<<GRID_SAGE, 256>>>(cw1, cb1);

    cudaFuncSetAttribute(edge_mma_kernel,
                         cudaFuncAttributeMaxDynamicSharedMemorySize, EDGE_SMEM_TOTAL);
    edge_mma_kernel<<<148, 512, EDGE_SMEM_TOTAL>>>(
        ei, ea, cw1, cw2, cb2, cw3, cb3, out);
}

// round 7
// speedup vs baseline: 2.2124x; 1.1383x over previous
#include <cuda_runtime.h>
#include <cuda_bf16.h>
#include <cstdint>

#define N_NODES 100000
#define N_EDGES 1200000
#define HID 64

// ---------------- device scratch (no allocations allowed) ----------------
__device__ int   g_cnt[N_NODES];
__device__ int   g_rowstart[N_NODES + 1];
__device__ int   g_cursor[N_NODES];
__device__ int   g_bsum[128];
__device__ int   g_boff[128];
__device__ int   g_esrc[N_EDGES];
__device__ float g_h[(size_t)N_NODES * HID];
__device__ float g_z[(size_t)N_NODES * HID];
__device__ float g_A[(size_t)N_NODES * HID];   // z @ Ws + cb1
__device__ float g_B[(size_t)N_NODES * HID];   // z @ Wd
__device__ int   g_is64;

// ---------------- helpers -------------------------------------------------
__device__ __forceinline__ void bf16_split(float v, float& hi, float& lo) {
    __nv_bfloat16 h = __float2bfloat16(v);
    hi = __bfloat162float(h);
    lo = v - hi;
}
__device__ __forceinline__ uint32_t pack2(float a, float b) {
    __nv_bfloat162 h = __floats2bfloat162_rn(a, b);
    return *(uint32_t*)&h;
}
// mma.sync m16n8k16 bf16 (A row-major frag, B col-major frag), f32 accum
__device__ __forceinline__ void hmma(float* d, const uint4 a, const uint2 b) {
    asm volatile("mma.sync.aligned.m16n8k16.row.col.f32.bf16.bf16.f32 "
        "{%0,%1,%2,%3}, {%4,%5,%6,%7}, {%8,%9}, {%0,%1,%2,%3};"
        : "+f"(d[0]), "+f"(d[1]), "+f"(d[2]), "+f"(d[3])
        : "r"(a.x), "r"(a.y), "r"(a.z), "r"(a.w), "r"(b.x), "r"(b.y));
}

// ---------------- dtype detection for edge_index (int64 vs int32) --------
__global__ void detect_kernel(const void* ei) {
    int lane = threadIdx.x;
    const long long* p = (const long long*)ei;
    int ok = 1;
    for (int i = lane; i < 256; i += 32) {
        long long v = p[i];
        if (v < 0 || v >= N_NODES) ok = 0;
    }
    ok = __all_sync(0xffffffffu, ok);
    if (lane == 0) g_is64 = ok;
}

__device__ __forceinline__ int load_idx(const void* ei, long long i, int is64) {
    if (is64) return (int)((const long long*)ei)[i];
    return ((const int*)ei)[i];
}

// ---------------- CSR build ----------------
__global__ void zero_cnt_kernel() {
    int i = blockIdx.x * blockDim.x + threadIdx.x;
    if (i < N_NODES) g_cnt[i] = 0;
}

__global__ void hist_kernel(const void* __restrict__ ei) {
    int is64 = g_is64;
    int e = blockIdx.x * blockDim.x + threadIdx.x;
    if (e < N_EDGES) {
        int dst = load_idx(ei, (long long)N_EDGES + e, is64);
        atomicAdd(&g_cnt[dst], 1);
    }
}

__global__ void scan1_kernel() {
    __shared__ int s[1024];
    int t = threadIdx.x;
    int i = blockIdx.x * 1024 + t;
    int v = (i < N_NODES) ? g_cnt[i] : 0;
    s[t] = v;
    __syncthreads();
    for (int off = 1; off < 1024; off <<= 1) {
        int u = (t >= off) ? s[t - off] : 0;
        __syncthreads();
        s[t] += u;
        __syncthreads();
    }
    if (i < N_NODES) g_rowstart[i] = s[t] - v;
    if (t == 1023) g_bsum[blockIdx.x] = s[1023];
}

__global__ void scan2_kernel(int nblocks) {
    __shared__ int s[128];
    int t = threadIdx.x;
    int v = (t < nblocks) ? g_bsum[t] : 0;
    s[t] = v;
    __syncthreads();
    for (int off = 1; off < 128; off <<= 1) {
        int u = (t >= off) ? s[t - off] : 0;
        __syncthreads();
        s[t] += u;
        __syncthreads();
    }
    g_boff[t] = s[t] - v;
}

__global__ void scan3_kernel() {
    int i = blockIdx.x * blockDim.x + threadIdx.x;
    if (i < N_NODES) {
        int r = g_rowstart[i] + g_boff[i >> 10];
        g_rowstart[i] = r;
        g_cursor[i] = r;
    }
    if (i == 0) g_rowstart[N_NODES] = N_EDGES;
}

__global__ void fill_kernel(const void* __restrict__ ei) {
    int is64 = g_is64;
    int e = blockIdx.x * blockDim.x + threadIdx.x;
    if (e < N_EDGES) {
        int dst = load_idx(ei, (long long)N_EDGES + e, is64);
        int src = load_idx(ei, (long long)e, is64);
        int p = atomicAdd(&g_cursor[dst], 1);
        g_esrc[p] = src;
    }
}

// ---------------- SAGE layer: fused agg + GEMM + LN + ReLU ---------------
// fp32, 4 nodes/warp, transposed float4 weights (LDS-amortized).
__global__ void __launch_bounds__(128) sage_kernel(
    const float* __restrict__ x0, int layer,
    const float* __restrict__ wl, const float* __restrict__ wr,
    const float* __restrict__ bias, const float* __restrict__ lng,
    const float* __restrict__ lnb)
{
    __shared__ __align__(16) float wl_t[64 * 68];   // [feat][k]
    __shared__ __align__(16) float wr_t[64 * 68];
    __shared__ __align__(16) float nb[4 * 4 * 128]; // warp x node x (mean64|x64)
    __shared__ float b_s[64], g_s[64], bb_s[64];

    const float* xin = (layer == 0) ? x0 : g_h;
    float* xout = (layer == 0) ? g_h : g_z;

    int tid = threadIdx.x;
    for (int i = tid; i < 64 * 64; i += 128) {
        int k = i >> 6, f = i & 63;
        wl_t[f * 68 + k] = wl[i];
        wr_t[f * 68 + k] = wr[i];
    }
    if (tid < 64) { b_s[tid] = bias[tid]; g_s[tid] = lng[tid]; bb_s[tid] = lnb[tid]; }
    __syncthreads();

    int w = tid >> 5, lane = tid & 31;
    float* mynb = nb + w * 512;

    for (int base = blockIdx.x * 16; base < N_NODES; base += gridDim.x * 16) {
        int n0 = base + w * 4;

        // ---- aggregate 4 nodes: mean + x into per-warp smem ----
        #pragma unroll
        for (int t = 0; t < 4; t++) {
            int node = n0 + t;
            if (node < N_NODES) {
                int rs = g_rowstart[node], re = g_rowstart[node + 1];
                float a0 = 0.f, a1 = 0.f;
                for (int i = rs; i < re; i++) {
                    int src = g_esrc[i];
                    const float* xp = xin + (size_t)src * 64;
                    a0 += xp[lane];
                    a1 += xp[lane + 32];
                }
                float inv = 1.f / (float)max(re - rs, 1);
                const float* xn = xin + (size_t)node * 64;
                mynb[t * 128 + lane]      = a0 * inv;
                mynb[t * 128 + lane + 32] = a1 * inv;
                mynb[t * 128 + 64 + lane]      = xn[lane];
                mynb[t * 128 + 96 + lane]      = xn[lane + 32];
            } else {
                mynb[t * 128 + lane]      = 0.f;
                mynb[t * 128 + lane + 32] = 0.f;
                mynb[t * 128 + 64 + lane] = 0.f;
                mynb[t * 128 + 96 + lane] = 0.f;
            }
        }
        __syncwarp();

        // ---- GEMM: 4 nodes x 2 feats per lane ----
        float acc[4][2];
        #pragma unroll
        for (int t = 0; t < 4; t++) { acc[t][0] = b_s[lane]; acc[t][1] = b_s[lane + 32]; }
        #pragma unroll 4
        for (int k4 = 0; k4 < 16; k4++) {
            float4 u0 = *(const float4*)&wl_t[lane * 68 + k4 * 4];
            float4 u1 = *(const float4*)&wl_t[(lane + 32) * 68 + k4 * 4];
            float4 v0 = *(const float4*)&wr_t[lane * 68 + k4 * 4];
            float4 v1 = *(const float4*)&wr_t[(lane + 32) * 68 + k4 * 4];
            #pragma unroll
            for (int t = 0; t < 4; t++) {
                float4 m  = *(const float4*)&mynb[t * 128 + k4 * 4];
                float4 xv = *(const float4*)&mynb[t * 128 + 64 + k4 * 4];
                acc[t][0] += m.x * u0.x + m.y * u0.y + m.z * u0.z + m.w * u0.w
                           + xv.x * v0.x + xv.y * v0.y + xv.z * v0.z + xv.w * v0.w;
                acc[t][1] += m.x * u1.x + m.y * u1.y + m.z * u1.z + m.w * u1.w
                           + xv.x * v1.x + xv.y * v1.y + xv.z * v1.z + xv.w * v1.w;
            }
        }

        // ---- LN + ReLU per node (round-4 proven math) ----
        #pragma unroll
        for (int t = 0; t < 4; t++) {
            int node = n0 + t;
            if (node >= N_NODES) continue;   // warp-uniform branch
            float o0 = acc[t][0], o1 = acc[t][1];
            float ssum = o0 + o1;
            #pragma unroll
            for (int off = 16; off > 0; off >>= 1) ssum += __shfl_xor_sync(0xffffffffu, ssum, off);
            float mu = ssum * (1.f / 64.f);
            float d0 = o0 - mu, d1 = o1 - mu;
            float vsum = d0 * d0 + d1 * d1;
            #pragma unroll
            for (int off = 16; off > 0; off >>= 1) vsum += __shfl_xor_sync(0xffffffffu, vsum, off);
            float rstd = rsqrtf(vsum * (1.f / 64.f) + 1e-5f);
            float r0 = d0 * rstd * g_s[lane]      + bb_s[lane];
            float r1 = d1 * rstd * g_s[lane + 32] + bb_s[lane + 32];
            xout[(size_t)node * 64 + lane]      = fmaxf(r0, 0.f);
            xout[(size_t)node * 64 + lane + 32] = fmaxf(r1, 0.f);
        }
        __syncwarp();
    }
}

// ---------------- per-node precompute: A = z@Ws + cb1, B = z@Wd ----------
// fp32, 4 nodes/warp, transposed float4 weights.
__global__ void __launch_bounds__(128) node_pre_kernel(
    const float* __restrict__ cw1, const float* __restrict__ cb1)
{
    __shared__ __align__(16) float ws_t[64 * 68];
    __shared__ __align__(16) float wd_t[64 * 68];
    __shared__ __align__(16) float zb[4 * 4 * 64];
    __shared__ float cb_s[64];

    int tid = threadIdx.x;
    for (int i = tid; i < 64 * 64; i += 128) {
        int k = i >> 6, f = i & 63;
        ws_t[f * 68 + k] = cw1[i];
        wd_t[f * 68 + k] = cw1[64 * 64 + i];
    }
    if (tid < 64) cb_s[tid] = cb1[tid];
    __syncthreads();

    int w = tid >> 5, lane = tid & 31;
    float* myz = zb + w * 256;

    for (int base = blockIdx.x * 16; base < N_NODES; base += gridDim.x * 16) {
        int n0 = base + w * 4;
        #pragma unroll
        for (int t = 0; t < 4; t++) {
            int node = n0 + t;
            if (node < N_NODES) {
                const float* zp = g_z + (size_t)node * 64;
                myz[t * 64 + lane]      = zp[lane];
                myz[t * 64 + lane + 32] = zp[lane + 32];
            } else {
                myz[t * 64 + lane]      = 0.f;
                myz[t * 64 + lane + 32] = 0.f;
            }
        }
        __syncwarp();

        float a[4][2], b[4][2];
        #pragma unroll
        for (int t = 0; t < 4; t++) {
            a[t][0] = cb_s[lane]; a[t][1] = cb_s[lane + 32];
            b[t][0] = 0.f; b[t][1] = 0.f;
        }
        #pragma unroll 4
        for (int k4 = 0; k4 < 16; k4++) {
            float4 s0 = *(const float4*)&ws_t[lane * 68 + k4 * 4];
            float4 s1 = *(const float4*)&ws_t[(lane + 32) * 68 + k4 * 4];
            float4 d0 = *(const float4*)&wd_t[lane * 68 + k4 * 4];
            float4 d1 = *(const float4*)&wd_t[(lane + 32) * 68 + k4 * 4];
            #pragma unroll
            for (int t = 0; t < 4; t++) {
                float4 z = *(const float4*)&myz[t * 64 + k4 * 4];
                a[t][0] += z.x * s0.x + z.y * s0.y + z.z * s0.z + z.w * s0.w;
                a[t][1] += z.x * s1.x + z.y * s1.y + z.z * s1.z + z.w * s1.w;
                b[t][0] += z.x * d0.x + z.y * d0.y + z.z * d0.z + z.w * d0.w;
                b[t][1] += z.x * d1.x + z.y * d1.y + z.z * d1.z + z.w * d1.w;
            }
        }
        #pragma unroll
        for (int t = 0; t < 4; t++) {
            int node = n0 + t;
            if (node >= N_NODES) continue;
            g_A[(size_t)node * 64 + lane]      = a[t][0];
            g_A[(size_t)node * 64 + lane + 32] = a[t][1];
            g_B[(size_t)node * 64 + lane]      = b[t][0];
            g_B[(size_t)node * 64 + lane + 32] = b[t][1];
        }
        __syncwarp();
    }
}

// ================= Edge classifier via mma.sync bf16-split ================
// (verbatim round-4 passing code)
#define M_TILE 128
#define N_TILES (N_EDGES / M_TILE)   // 9375

#define OFF_A1   0                     // 8 rowgrp x 12 kstep x 512B = 49152
#define OFF_A2   49152                 // 8 x 8 x 512               = 32768
#define OFF_B1   81920                 // 8 ntile x 18 kstep x 256B = 36864
#define OFF_B2   118784                // 4 x 12 x 256              = 12288
#define OFF_BASE 131072                // 128 x 68 f32              = 34816
#define OFF_LOG  165888                // 128 f32                   = 512
#define OFF_CB2  166400
#define OFF_CW3  166528
#define EDGE_SMEM_TOTAL 166656

__device__ __forceinline__ uint32_t a1_off(int r, int c2) {
    return (uint32_t)(((r >> 4) * 12 + (c2 >> 3)) << 9)
         + (((r & 7) * 4 + (c2 & 3)) << 4)
         + ((((r >> 3) & 1) + 2 * ((c2 >> 2) & 1)) << 2);
}
__device__ __forceinline__ uint32_t a2_off(int r, int c2) {
    return (uint32_t)(((r >> 4) * 8 + (c2 >> 3)) << 9)
         + (((r & 7) * 4 + (c2 & 3)) << 4)
         + ((((r >> 3) & 1) + 2 * ((c2 >> 2) & 1)) << 2);
}

__global__ void __launch_bounds__(512, 1) edge_mma_kernel(
    const void* __restrict__ ei, const float* __restrict__ ea,
    const float* __restrict__ cw1,
    const float* __restrict__ cw2, const float* __restrict__ cb2,
    const float* __restrict__ cw3, const float* __restrict__ cb3,
    float* __restrict__ out)
{
    extern __shared__ char smem[];
    float* base_s = (float*)(smem + OFF_BASE);
    float* log_s  = (float*)(smem + OFF_LOG);
    float* cb2s   = (float*)(smem + OFF_CB2);
    float* cw3s   = (float*)(smem + OFF_CW3);

    const int tid = threadIdx.x;
    const int wid = tid >> 5, lane = tid & 31;
    const int q = lane & 3;

    for (int i = tid; i < 8 * 18 * 64; i += 512) {
        int nt = i / (18 * 64);
        int rem = i % (18 * 64);
        int ks = rem >> 6;
        int j = rem & 63;
        int ln = j >> 1, rg = j & 1;
        int n = nt * 8 + (ln >> 2);
        int k = ks * 16 + 2 * (ln & 3) + 8 * rg;
        int sec = k / 96, kr = k % 96;
        float w0 = cw1[(128 + kr) * 64 + n];
        float w1 = cw1[(128 + kr + 1) * 64 + n];
        float h0, l0, h1, l1;
        bf16_split(w0, h0, l0); bf16_split(w1, h1, l1);
        uint32_t v = (sec < 2) ? pack2(h0, h1) : pack2(l0, l1);
        *(uint32_t*)(smem + OFF_B1 + ((nt * 18 + ks) << 8) + ln * 8 + rg * 4) = v;
    }
    for (int i = tid; i < 4 * 12 * 64; i += 512) {
        int nt = i / (12 * 64);
        int rem = i % (12 * 64);
        int ks = rem >> 6;
        int j = rem & 63;
        int ln = j >> 1, rg = j & 1;
        int n = nt * 8 + (ln >> 2);
        int k = ks * 16 + 2 * (ln & 3) + 8 * rg;
        int sec = k / 64, kr = k % 64;
        float w0 = cw2[kr * 32 + n];
        float w1 = cw2[(kr + 1) * 32 + n];
        float h0, l0, h1, l1;
        bf16_split(w0, h0, l0); bf16_split(w1, h1, l1);
        uint32_t v = (sec < 2) ? pack2(h0, h1) : pack2(l0, l1);
        *(uint32_t*)(smem + OFF_B2 + ((nt * 12 + ks) << 8) + ln * 8 + rg * 4) = v;
    }
    if (tid < 32) { cb2s[tid] = cb2[tid]; cw3s[tid] = cw3[tid]; }
    if (tid < 128) log_s[tid] = 0.f;
    __syncthreads();

    const int is64 = g_is64;
    const float cb3v = cb3[0];
    const int rowgrp = wid & 7, nhalf = wid >> 3;

    for (int tile = blockIdx.x; tile < N_TILES; tile += gridDim.x) {
        const int e0 = tile * M_TILE;

        #pragma unroll 2
        for (int t = 0; t < 8; t++) {
            int r = wid * 8 + t;
            int e = e0 + r;
            int src = load_idx(ei, (long long)e, is64);
            int dst = load_idx(ei, (long long)N_EDGES + e, is64);
            float2 a = ((const float2*)(g_z + (size_t)src * 64))[lane];
            float2 b = ((const float2*)(g_z + (size_t)dst * 64))[lane];
            float px = a.x * b.x, py = a.y * b.y;
            float hx, lx, hy, ly;
            bf16_split(px, hx, lx); bf16_split(py, hy, ly);
            *(uint32_t*)(smem + OFF_A1 + a1_off(r, lane))      = pack2(hx, hy);
            *(uint32_t*)(smem + OFF_A1 + a1_off(r, lane + 48)) = pack2(lx, ly);
            if (lane < 16) {
                float2 e2 = ((const float2*)(ea + (size_t)e * 32))[lane];
                float eh0, el0, eh1, el1;
                bf16_split(e2.x, eh0, el0); bf16_split(e2.y, eh1, el1);
                *(uint32_t*)(smem + OFF_A1 + a1_off(r, 32 + lane)) = pack2(eh0, eh1);
                *(uint32_t*)(smem + OFF_A1 + a1_off(r, 80 + lane)) = pack2(el0, el1);
            }
            float2 av = ((const float2*)(g_A + (size_t)src * 64))[lane];
            float2 bv = ((const float2*)(g_B + (size_t)dst * 64))[lane];
            base_s[r * 68 + 2 * lane]     = av.x + bv.x;
            base_s[r * 68 + 2 * lane + 1] = av.y + bv.y;
        }
        __syncthreads();

        float d[4][4] = {};
        #pragma unroll
        for (int s = 0; s < 18; s++) {
            int aks = (s < 12) ? s : s - 12;
            uint4 A = *(const uint4*)(smem + OFF_A1 + ((rowgrp * 12 + aks) << 9) + lane * 16);
            #pragma unroll
            for (int nt = 0; nt < 4; nt++) {
                int ntg = nhalf * 4 + nt;
                uint2 B = *(const uint2*)(smem + OFF_B1 + ((ntg * 18 + s) << 8) + lane * 8);
                hmma(d[nt], A, B);
            }
        }

        {
            int r0 = rowgrp * 16 + (lane >> 2);
            #pragma unroll
            for (int nt = 0; nt < 4; nt++) {
                int c0 = nhalf * 32 + nt * 8 + 2 * q;
                float v00 = fmaxf(d[nt][0] + base_s[r0 * 68 + c0], 0.f);
                float v01 = fmaxf(d[nt][1] + base_s[r0 * 68 + c0 + 1], 0.f);
                float v10 = fmaxf(d[nt][2] + base_s[(r0 + 8) * 68 + c0], 0.f);
                float v11 = fmaxf(d[nt][3] + base_s[(r0 + 8) * 68 + c0 + 1], 0.f);
                float h00, l00, h01, l01, h10, l10, h11, l11;
                bf16_split(v00, h00, l00); bf16_split(v01, h01, l01);
                bf16_split(v10, h10, l10); bf16_split(v11, h11, l11);
                int c2 = c0 >> 1;
                *(uint32_t*)(smem + OFF_A2 + a2_off(r0,     c2))      = pack2(h00, h01);
                *(uint32_t*)(smem + OFF_A2 + a2_off(r0 + 8, c2))      = pack2(h10, h11);
                *(uint32_t*)(smem + OFF_A2 + a2_off(r0,     c2 + 32)) = pack2(l00, l01);
                *(uint32_t*)(smem + OFF_A2 + a2_off(r0 + 8, c2 + 32)) = pack2(l10, l11);
            }
        }
        __syncthreads();

        float e2a[2][4] = {};
        #pragma unroll
        for (int s = 0; s < 12; s++) {
            int aks = (s < 8) ? s : s - 8;
            uint4 A = *(const uint4*)(smem + OFF_A2 + ((rowgrp * 8 + aks) << 9) + lane * 16);
            #pragma unroll
            for (int nt = 0; nt < 2; nt++) {
                int ntg = nhalf * 2 + nt;
                uint2 B = *(const uint2*)(smem + OFF_B2 + ((ntg * 12 + s) << 8) + lane * 8);
                hmma(e2a[nt], A, B);
            }
        }

        {
            float p0 = 0.f, p1 = 0.f;
            #pragma unroll
            for (int nt = 0; nt < 2; nt++) {
                int c0 = nhalf * 16 + nt * 8 + 2 * q;
                float w0 = cw3s[c0], w1 = cw3s[c0 + 1];
                float b0 = cb2s[c0], b1 = cb2s[c0 + 1];
                p0 += fmaxf(e2a[nt][0] + b0, 0.f) * w0 + fmaxf(e2a[nt][1] + b1, 0.f) * w1;
                p1 += fmaxf(e2a[nt][2] + b0, 0.f) * w0 + fmaxf(e2a[nt][3] + b1, 0.f) * w1;
            }
            p0 += __shfl_xor_sync(0xffffffffu, p0, 1);
            p0 += __shfl_xor_sync(0xffffffffu, p0, 2);
            p1 += __shfl_xor_sync(0xffffffffu, p1, 1);
            p1 += __shfl_xor_sync(0xffffffffu, p1, 2);
            if (q == 0) {
                int r0 = rowgrp * 16 + (lane >> 2);
                atomicAdd(&log_s[r0], p0);
                atomicAdd(&log_s[r0 + 8], p1);
            }
        }
        __syncthreads();

        if (tid < 128) {
            out[e0 + tid] = log_s[tid] + cb3v;
            log_s[tid] = 0.f;
        }
    }
}

// ---------------- launch ----------------
extern "C" void kernel_launch(void* const* d_in, const int* in_sizes, int n_in,
                              void* d_out, int out_size)
{
    const float* x   = (const float*)d_in[0];
    const void*  ei  = (const void*)d_in[1];
    const float* ea  = (const float*)d_in[2];
    const float* wl0 = (const float*)d_in[3];
    const float* wr0 = (const float*)d_in[4];
    const float* b0  = (const float*)d_in[5];
    const float* g0  = (const float*)d_in[6];
    const float* bb0 = (const float*)d_in[7];
    const float* wl1 = (const float*)d_in[8];
    const float* wr1 = (const float*)d_in[9];
    const float* b1  = (const float*)d_in[10];
    const float* g1  = (const float*)d_in[11];
    const float* bb1 = (const float*)d_in[12];
    const float* cw1 = (const float*)d_in[13];
    const float* cb1 = (const float*)d_in[14];
    const float* cw2 = (const float*)d_in[15];
    const float* cb2 = (const float*)d_in[16];
    const float* cw3 = (const float*)d_in[17];
    const float* cb3 = (const float*)d_in[18];
    float* out = (float*)d_out;

    const int SCAN_BLOCKS = (N_NODES + 1023) / 1024;  // 98

    detect_kernel<<<1, 32>>>(ei);
    zero_cnt_kernel<<<(N_NODES + 255) / 256, 256>>>();
    hist_kernel<<<(N_EDGES + 255) / 256, 256>>>(ei);
    scan1_kernel<<<SCAN_BLOCKS, 1024>>>();
    scan2_kernel<<<1, 128>>>(SCAN_BLOCKS);
    scan3_kernel<<<(N_NODES + 255) / 256, 256>>>();
    fill_kernel<<<(N_EDGES + 255) / 256, 256>>>(ei);

    sage_kernel<<<1480, 128>>>(x, 0, wl0, wr0, b0, g0, bb0);
    sage_kernel<<<1480, 128>>>(x, 1, wl1, wr1, b1, g1, bb1);
    node_pre_kernel<<<1480, 128>>>(cw1, cb1);

    cudaFuncSetAttribute(edge_mma_kernel,
                         cudaFuncAttributeMaxDynamicSharedMemorySize, EDGE_SMEM_TOTAL);
    edge_mma_kernel<<<148, 512, EDGE_SMEM_TOTAL>>>(
        ei, ea, cw1, cw2, cb2, cw3, cb3, out);
}

// round 8
// speedup vs baseline: 2.6091x; 1.1793x over previous
#include <cuda_runtime.h>
#include <cuda_bf16.h>
#include <cstdint>

#define N_NODES 100000
#define N_EDGES 1200000
#define HID 64

// ---------------- device scratch (no allocations allowed) ----------------
__device__ int   g_cnt[N_NODES];
__device__ int   g_rowstart[N_NODES + 1];
__device__ int   g_cursor[N_NODES];
__device__ int   g_bsum[128];
__device__ int   g_boff[128];
__device__ int   g_esrc[N_EDGES];
__device__ float g_h[(size_t)N_NODES * HID];
__device__ float g_z[(size_t)N_NODES * HID];
__device__ float g_A[(size_t)N_NODES * HID];   // z @ Ws + cb1
__device__ float g_B[(size_t)N_NODES * HID];   // z @ Wd
__device__ int   g_is64;

// ---------------- helpers -------------------------------------------------
__device__ __forceinline__ void bf16_split(float v, float& hi, float& lo) {
    __nv_bfloat16 h = __float2bfloat16(v);
    hi = __bfloat162float(h);
    lo = v - hi;
}
__device__ __forceinline__ uint32_t pack2(float a, float b) {
    __nv_bfloat162 h = __floats2bfloat162_rn(a, b);
    return *(uint32_t*)&h;
}
// mma.sync m16n8k16 bf16 (A row-major frag, B col-major frag), f32 accum
__device__ __forceinline__ void hmma(float* d, const uint4 a, const uint2 b) {
    asm volatile("mma.sync.aligned.m16n8k16.row.col.f32.bf16.bf16.f32 "
        "{%0,%1,%2,%3}, {%4,%5,%6,%7}, {%8,%9}, {%0,%1,%2,%3};"
        : "+f"(d[0]), "+f"(d[1]), "+f"(d[2]), "+f"(d[3])
        : "r"(a.x), "r"(a.y), "r"(a.z), "r"(a.w), "r"(b.x), "r"(b.y));
}

// ---------------- dtype detection for edge_index (int64 vs int32) --------
__global__ void detect_kernel(const void* ei) {
    int lane = threadIdx.x;
    const long long* p = (const long long*)ei;
    int ok = 1;
    for (int i = lane; i < 256; i += 32) {
        long long v = p[i];
        if (v < 0 || v >= N_NODES) ok = 0;
    }
    ok = __all_sync(0xffffffffu, ok);
    if (lane == 0) g_is64 = ok;
}

__device__ __forceinline__ int load_idx(const void* ei, long long i, int is64) {
    if (is64) return (int)((const long long*)ei)[i];
    return ((const int*)ei)[i];
}

// ---------------- CSR build ----------------
__global__ void zero_cnt_kernel() {
    int i = blockIdx.x * blockDim.x + threadIdx.x;
    if (i < N_NODES) g_cnt[i] = 0;
}

__global__ void hist_kernel(const void* __restrict__ ei) {
    int is64 = g_is64;
    int e = blockIdx.x * blockDim.x + threadIdx.x;
    if (e < N_EDGES) {
        int dst = load_idx(ei, (long long)N_EDGES + e, is64);
        atomicAdd(&g_cnt[dst], 1);
    }
}

__global__ void scan1_kernel() {
    __shared__ int s[1024];
    int t = threadIdx.x;
    int i = blockIdx.x * 1024 + t;
    int v = (i < N_NODES) ? g_cnt[i] : 0;
    s[t] = v;
    __syncthreads();
    for (int off = 1; off < 1024; off <<= 1) {
        int u = (t >= off) ? s[t - off] : 0;
        __syncthreads();
        s[t] += u;
        __syncthreads();
    }
    if (i < N_NODES) g_rowstart[i] = s[t] - v;
    if (t == 1023) g_bsum[blockIdx.x] = s[1023];
}

__global__ void scan2_kernel(int nblocks) {
    __shared__ int s[128];
    int t = threadIdx.x;
    int v = (t < nblocks) ? g_bsum[t] : 0;
    s[t] = v;
    __syncthreads();
    for (int off = 1; off < 128; off <<= 1) {
        int u = (t >= off) ? s[t - off] : 0;
        __syncthreads();
        s[t] += u;
        __syncthreads();
    }
    g_boff[t] = s[t] - v;
}

__global__ void scan3_kernel() {
    int i = blockIdx.x * blockDim.x + threadIdx.x;
    if (i < N_NODES) {
        int r = g_rowstart[i] + g_boff[i >> 10];
        g_rowstart[i] = r;
        g_cursor[i] = r;
    }
    if (i == 0) g_rowstart[N_NODES] = N_EDGES;
}

__global__ void fill_kernel(const void* __restrict__ ei) {
    int is64 = g_is64;
    int e = blockIdx.x * blockDim.x + threadIdx.x;
    if (e < N_EDGES) {
        int dst = load_idx(ei, (long long)N_EDGES + e, is64);
        int src = load_idx(ei, (long long)e, is64);
        int p = atomicAdd(&g_cursor[dst], 1);
        g_esrc[p] = src;
    }
}

// ---------------- SAGE layer: fused agg + GEMM + LN + ReLU ---------------
// (round-7 proven)
__global__ void __launch_bounds__(128) sage_kernel(
    const float* __restrict__ x0, int layer,
    const float* __restrict__ wl, const float* __restrict__ wr,
    const float* __restrict__ bias, const float* __restrict__ lng,
    const float* __restrict__ lnb)
{
    __shared__ __align__(16) float wl_t[64 * 68];   // [feat][k]
    __shared__ __align__(16) float wr_t[64 * 68];
    __shared__ __align__(16) float nb[4 * 4 * 128]; // warp x node x (mean64|x64)
    __shared__ float b_s[64], g_s[64], bb_s[64];

    const float* xin = (layer == 0) ? x0 : g_h;
    float* xout = (layer == 0) ? g_h : g_z;

    int tid = threadIdx.x;
    for (int i = tid; i < 64 * 64; i += 128) {
        int k = i >> 6, f = i & 63;
        wl_t[f * 68 + k] = wl[i];
        wr_t[f * 68 + k] = wr[i];
    }
    if (tid < 64) { b_s[tid] = bias[tid]; g_s[tid] = lng[tid]; bb_s[tid] = lnb[tid]; }
    __syncthreads();

    int w = tid >> 5, lane = tid & 31;
    float* mynb = nb + w * 512;

    for (int base = blockIdx.x * 16; base < N_NODES; base += gridDim.x * 16) {
        int n0 = base + w * 4;

        #pragma unroll
        for (int t = 0; t < 4; t++) {
            int node = n0 + t;
            if (node < N_NODES) {
                int rs = g_rowstart[node], re = g_rowstart[node + 1];
                float a0 = 0.f, a1 = 0.f;
                for (int i = rs; i < re; i++) {
                    int src = g_esrc[i];
                    const float* xp = xin + (size_t)src * 64;
                    a0 += xp[lane];
                    a1 += xp[lane + 32];
                }
                float inv = 1.f / (float)max(re - rs, 1);
                const float* xn = xin + (size_t)node * 64;
                mynb[t * 128 + lane]      = a0 * inv;
                mynb[t * 128 + lane + 32] = a1 * inv;
                mynb[t * 128 + 64 + lane]      = xn[lane];
                mynb[t * 128 + 96 + lane]      = xn[lane + 32];
            } else {
                mynb[t * 128 + lane]      = 0.f;
                mynb[t * 128 + lane + 32] = 0.f;
                mynb[t * 128 + 64 + lane] = 0.f;
                mynb[t * 128 + 96 + lane] = 0.f;
            }
        }
        __syncwarp();

        float acc[4][2];
        #pragma unroll
        for (int t = 0; t < 4; t++) { acc[t][0] = b_s[lane]; acc[t][1] = b_s[lane + 32]; }
        #pragma unroll 4
        for (int k4 = 0; k4 < 16; k4++) {
            float4 u0 = *(const float4*)&wl_t[lane * 68 + k4 * 4];
            float4 u1 = *(const float4*)&wl_t[(lane + 32) * 68 + k4 * 4];
            float4 v0 = *(const float4*)&wr_t[lane * 68 + k4 * 4];
            float4 v1 = *(const float4*)&wr_t[(lane + 32) * 68 + k4 * 4];
            #pragma unroll
            for (int t = 0; t < 4; t++) {
                float4 m  = *(const float4*)&mynb[t * 128 + k4 * 4];
                float4 xv = *(const float4*)&mynb[t * 128 + 64 + k4 * 4];
                acc[t][0] += m.x * u0.x + m.y * u0.y + m.z * u0.z + m.w * u0.w
                           + xv.x * v0.x + xv.y * v0.y + xv.z * v0.z + xv.w * v0.w;
                acc[t][1] += m.x * u1.x + m.y * u1.y + m.z * u1.z + m.w * u1.w
                           + xv.x * v1.x + xv.y * v1.y + xv.z * v1.z + xv.w * v1.w;
            }
        }

        #pragma unroll
        for (int t = 0; t < 4; t++) {
            int node = n0 + t;
            if (node >= N_NODES) continue;
            float o0 = acc[t][0], o1 = acc[t][1];
            float ssum = o0 + o1;
            #pragma unroll
            for (int off = 16; off > 0; off >>= 1) ssum += __shfl_xor_sync(0xffffffffu, ssum, off);
            float mu = ssum * (1.f / 64.f);
            float d0 = o0 - mu, d1 = o1 - mu;
            float vsum = d0 * d0 + d1 * d1;
            #pragma unroll
            for (int off = 16; off > 0; off >>= 1) vsum += __shfl_xor_sync(0xffffffffu, vsum, off);
            float rstd = rsqrtf(vsum * (1.f / 64.f) + 1e-5f);
            float r0 = d0 * rstd * g_s[lane]      + bb_s[lane];
            float r1 = d1 * rstd * g_s[lane + 32] + bb_s[lane + 32];
            xout[(size_t)node * 64 + lane]      = fmaxf(r0, 0.f);
            xout[(size_t)node * 64 + lane + 32] = fmaxf(r1, 0.f);
        }
        __syncwarp();
    }
}

// ---------------- per-node precompute (round-7 proven) -------------------
__global__ void __launch_bounds__(128) node_pre_kernel(
    const float* __restrict__ cw1, const float* __restrict__ cb1)
{
    __shared__ __align__(16) float ws_t[64 * 68];
    __shared__ __align__(16) float wd_t[64 * 68];
    __shared__ __align__(16) float zb[4 * 4 * 64];
    __shared__ float cb_s[64];

    int tid = threadIdx.x;
    for (int i = tid; i < 64 * 64; i += 128) {
        int k = i >> 6, f = i & 63;
        ws_t[f * 68 + k] = cw1[i];
        wd_t[f * 68 + k] = cw1[64 * 64 + i];
    }
    if (tid < 64) cb_s[tid] = cb1[tid];
    __syncthreads();

    int w = tid >> 5, lane = tid & 31;
    float* myz = zb + w * 256;

    for (int base = blockIdx.x * 16; base < N_NODES; base += gridDim.x * 16) {
        int n0 = base + w * 4;
        #pragma unroll
        for (int t = 0; t < 4; t++) {
            int node = n0 + t;
            if (node < N_NODES) {
                const float* zp = g_z + (size_t)node * 64;
                myz[t * 64 + lane]      = zp[lane];
                myz[t * 64 + lane + 32] = zp[lane + 32];
            } else {
                myz[t * 64 + lane]      = 0.f;
                myz[t * 64 + lane + 32] = 0.f;
            }
        }
        __syncwarp();

        float a[4][2], b[4][2];
        #pragma unroll
        for (int t = 0; t < 4; t++) {
            a[t][0] = cb_s[lane]; a[t][1] = cb_s[lane + 32];
            b[t][0] = 0.f; b[t][1] = 0.f;
        }
        #pragma unroll 4
        for (int k4 = 0; k4 < 16; k4++) {
            float4 s0 = *(const float4*)&ws_t[lane * 68 + k4 * 4];
            float4 s1 = *(const float4*)&ws_t[(lane + 32) * 68 + k4 * 4];
            float4 d0 = *(const float4*)&wd_t[lane * 68 + k4 * 4];
            float4 d1 = *(const float4*)&wd_t[(lane + 32) * 68 + k4 * 4];
            #pragma unroll
            for (int t = 0; t < 4; t++) {
                float4 z = *(const float4*)&myz[t * 64 + k4 * 4];
                a[t][0] += z.x * s0.x + z.y * s0.y + z.z * s0.z + z.w * s0.w;
                a[t][1] += z.x * s1.x + z.y * s1.y + z.z * s1.z + z.w * s1.w;
                b[t][0] += z.x * d0.x + z.y * d0.y + z.z * d0.z + z.w * d0.w;
                b[t][1] += z.x * d1.x + z.y * d1.y + z.z * d1.z + z.w * d1.w;
            }
        }
        #pragma unroll
        for (int t = 0; t < 4; t++) {
            int node = n0 + t;
            if (node >= N_NODES) continue;
            g_A[(size_t)node * 64 + lane]      = a[t][0];
            g_A[(size_t)node * 64 + lane + 32] = a[t][1];
            g_B[(size_t)node * 64 + lane]      = b[t][0];
            g_B[(size_t)node * 64 + lane + 32] = b[t][1];
        }
        __syncwarp();
    }
}

// ================= Edge classifier via mma.sync bf16-split ================
// M_TILE=64 -> smem 108KB -> 2 CTAs/SM (phase overlap across CTAs).
#define M_TILE 64
#define N_TILES (N_EDGES / M_TILE)   // 18750

#define OFF_A1   0                     // 4 rowgrp x 12 kstep x 512B = 24576
#define OFF_A2   24576                 // 4 x 8 x 512               = 16384
#define OFF_B1   40960                 // 8 ntile x 18 kstep x 256B = 36864
#define OFF_B2   77824                 // 4 x 12 x 256              = 12288
#define OFF_BASE 90112                 // 64 x 68 f32               = 17408
#define OFF_LOG  107520                // 64 f32 (pad 256)
#define OFF_CB2  107776
#define OFF_CW3  107904
#define EDGE_SMEM_TOTAL 108032

__device__ __forceinline__ uint32_t a1_off(int r, int c2) {
    return (uint32_t)(((r >> 4) * 12 + (c2 >> 3)) << 9)
         + (((r & 7) * 4 + (c2 & 3)) << 4)
         + ((((r >> 3) & 1) + 2 * ((c2 >> 2) & 1)) << 2);
}
__device__ __forceinline__ uint32_t a2_off(int r, int c2) {
    return (uint32_t)(((r >> 4) * 8 + (c2 >> 3)) << 9)
         + (((r & 7) * 4 + (c2 & 3)) << 4)
         + ((((r >> 3) & 1) + 2 * ((c2 >> 2) & 1)) << 2);
}

__global__ void __launch_bounds__(512, 2) edge_mma_kernel(
    const void* __restrict__ ei, const float* __restrict__ ea,
    const float* __restrict__ cw1,
    const float* __restrict__ cw2, const float* __restrict__ cb2,
    const float* __restrict__ cw3, const float* __restrict__ cb3,
    float* __restrict__ out)
{
    extern __shared__ char smem[];
    float* base_s = (float*)(smem + OFF_BASE);
    float* log_s  = (float*)(smem + OFF_LOG);
    float* cb2s   = (float*)(smem + OFF_CB2);
    float* cw3s   = (float*)(smem + OFF_CW3);

    const int tid = threadIdx.x;
    const int wid = tid >> 5, lane = tid & 31;
    const int q = lane & 3;

    // ---- weight prologue (identical fragment layout to round-4/7) ----
    for (int i = tid; i < 8 * 18 * 64; i += 512) {
        int nt = i / (18 * 64);
        int rem = i % (18 * 64);
        int ks = rem >> 6;
        int j = rem & 63;
        int ln = j >> 1, rg = j & 1;
        int n = nt * 8 + (ln >> 2);
        int k = ks * 16 + 2 * (ln & 3) + 8 * rg;
        int sec = k / 96, kr = k % 96;
        float w0 = cw1[(128 + kr) * 64 + n];
        float w1 = cw1[(128 + kr + 1) * 64 + n];
        float h0, l0, h1, l1;
        bf16_split(w0, h0, l0); bf16_split(w1, h1, l1);
        uint32_t v = (sec < 2) ? pack2(h0, h1) : pack2(l0, l1);
        *(uint32_t*)(smem + OFF_B1 + ((nt * 18 + ks) << 8) + ln * 8 + rg * 4) = v;
    }
    for (int i = tid; i < 4 * 12 * 64; i += 512) {
        int nt = i / (12 * 64);
        int rem = i % (12 * 64);
        int ks = rem >> 6;
        int j = rem & 63;
        int ln = j >> 1, rg = j & 1;
        int n = nt * 8 + (ln >> 2);
        int k = ks * 16 + 2 * (ln & 3) + 8 * rg;
        int sec = k / 64, kr = k % 64;
        float w0 = cw2[kr * 32 + n];
        float w1 = cw2[(kr + 1) * 32 + n];
        float h0, l0, h1, l1;
        bf16_split(w0, h0, l0); bf16_split(w1, h1, l1);
        uint32_t v = (sec < 2) ? pack2(h0, h1) : pack2(l0, l1);
        *(uint32_t*)(smem + OFF_B2 + ((nt * 12 + ks) << 8) + ln * 8 + rg * 4) = v;
    }
    if (tid < 32) { cb2s[tid] = cb2[tid]; cw3s[tid] = cw3[tid]; }
    if (tid < 64) log_s[tid] = 0.f;
    __syncthreads();

    const int is64 = g_is64;
    const float cb3v = cb3[0];
    // L1: warp = (rowgrp in [0,4), nquad in [0,4)); L2: (rowgrp, ncol in [0,4))
    const int rowgrp = wid & 3, nquad = wid >> 2;

    for (int tile = blockIdx.x; tile < N_TILES; tile += gridDim.x) {
        const int e0 = tile * M_TILE;

        // ---------------- gather: 16 warps x 4 edges ----------------
        #pragma unroll
        for (int t = 0; t < 4; t++) {
            int r = wid * 4 + t;
            int e = e0 + r;
            int src = load_idx(ei, (long long)e, is64);
            int dst = load_idx(ei, (long long)N_EDGES + e, is64);
            float2 a = ((const float2*)(g_z + (size_t)src * 64))[lane];
            float2 b = ((const float2*)(g_z + (size_t)dst * 64))[lane];
            float px = a.x * b.x, py = a.y * b.y;
            float hx, lx, hy, ly;
            bf16_split(px, hx, lx); bf16_split(py, hy, ly);
            *(uint32_t*)(smem + OFF_A1 + a1_off(r, lane))      = pack2(hx, hy);
            *(uint32_t*)(smem + OFF_A1 + a1_off(r, lane + 48)) = pack2(lx, ly);
            if (lane < 16) {
                float2 e2 = ((const float2*)(ea + (size_t)e * 32))[lane];
                float eh0, el0, eh1, el1;
                bf16_split(e2.x, eh0, el0); bf16_split(e2.y, eh1, el1);
                *(uint32_t*)(smem + OFF_A1 + a1_off(r, 32 + lane)) = pack2(eh0, eh1);
                *(uint32_t*)(smem + OFF_A1 + a1_off(r, 80 + lane)) = pack2(el0, el1);
            }
            float2 av = ((const float2*)(g_A + (size_t)src * 64))[lane];
            float2 bv = ((const float2*)(g_B + (size_t)dst * 64))[lane];
            base_s[r * 68 + 2 * lane]     = av.x + bv.x;
            base_s[r * 68 + 2 * lane + 1] = av.y + bv.y;
        }
        __syncthreads();

        // ---------------- L1 GEMM: 16 rows x 16 cols per warp ----------------
        float d[2][4] = {};
        #pragma unroll
        for (int s = 0; s < 18; s++) {
            int aks = (s < 12) ? s : s - 12;
            uint4 A = *(const uint4*)(smem + OFF_A1 + ((rowgrp * 12 + aks) << 9) + lane * 16);
            #pragma unroll
            for (int nt = 0; nt < 2; nt++) {
                int ntg = nquad * 2 + nt;
                uint2 B = *(const uint2*)(smem + OFF_B1 + ((ntg * 18 + s) << 8) + lane * 8);
                hmma(d[nt], A, B);
            }
        }

        // ---------------- epilogue 1: +base, relu, split -> A2 ----------------
        {
            int r0 = rowgrp * 16 + (lane >> 2);
            #pragma unroll
            for (int nt = 0; nt < 2; nt++) {
                int c0 = nquad * 16 + nt * 8 + 2 * q;
                float v00 = fmaxf(d[nt][0] + base_s[r0 * 68 + c0], 0.f);
                float v01 = fmaxf(d[nt][1] + base_s[r0 * 68 + c0 + 1], 0.f);
                float v10 = fmaxf(d[nt][2] + base_s[(r0 + 8) * 68 + c0], 0.f);
                float v11 = fmaxf(d[nt][3] + base_s[(r0 + 8) * 68 + c0 + 1], 0.f);
                float h00, l00, h01, l01, h10, l10, h11, l11;
                bf16_split(v00, h00, l00); bf16_split(v01, h01, l01);
                bf16_split(v10, h10, l10); bf16_split(v11, h11, l11);
                int c2 = c0 >> 1;
                *(uint32_t*)(smem + OFF_A2 + a2_off(r0,     c2))      = pack2(h00, h01);
                *(uint32_t*)(smem + OFF_A2 + a2_off(r0 + 8, c2))      = pack2(h10, h11);
                *(uint32_t*)(smem + OFF_A2 + a2_off(r0,     c2 + 32)) = pack2(l00, l01);
                *(uint32_t*)(smem + OFF_A2 + a2_off(r0 + 8, c2 + 32)) = pack2(l10, l11);
            }
        }
        __syncthreads();

        // ---------------- L2 GEMM: 16 rows x 8 cols per warp ----------------
        float e2a[4] = {};
        #pragma unroll
        for (int s = 0; s < 12; s++) {
            int aks = (s < 8) ? s : s - 8;
            uint4 A = *(const uint4*)(smem + OFF_A2 + ((rowgrp * 8 + aks) << 9) + lane * 16);
            uint2 B = *(const uint2*)(smem + OFF_B2 + ((nquad * 12 + s) << 8) + lane * 8);
            hmma(e2a, A, B);
        }

        // ---------------- epilogue 2: +cb2, relu, dot cw3, reduce ------------
        {
            int c0 = nquad * 8 + 2 * q;
            float w0 = cw3s[c0], w1 = cw3s[c0 + 1];
            float b0 = cb2s[c0], b1 = cb2s[c0 + 1];
            float p0 = fmaxf(e2a[0] + b0, 0.f) * w0 + fmaxf(e2a[1] + b1, 0.f) * w1;
            float p1 = fmaxf(e2a[2] + b0, 0.f) * w0 + fmaxf(e2a[3] + b1, 0.f) * w1;
            p0 += __shfl_xor_sync(0xffffffffu, p0, 1);
            p0 += __shfl_xor_sync(0xffffffffu, p0, 2);
            p1 += __shfl_xor_sync(0xffffffffu, p1, 1);
            p1 += __shfl_xor_sync(0xffffffffu, p1, 2);
            if (q == 0) {
                int r0 = rowgrp * 16 + (lane >> 2);
                atomicAdd(&log_s[r0], p0);
                atomicAdd(&log_s[r0 + 8], p1);
            }
        }
        __syncthreads();

        if (tid < 64) {
            out[e0 + tid] = log_s[tid] + cb3v;
            log_s[tid] = 0.f;
        }
    }
}

// ---------------- launch ----------------
extern "C" void kernel_launch(void* const* d_in, const int* in_sizes, int n_in,
                              void* d_out, int out_size)
{
    const float* x   = (const float*)d_in[0];
    const void*  ei  = (const void*)d_in[1];
    const float* ea  = (const float*)d_in[2];
    const float* wl0 = (const float*)d_in[3];
    const float* wr0 = (const float*)d_in[4];
    const float* b0  = (const float*)d_in[5];
    const float* g0  = (const float*)d_in[6];
    const float* bb0 = (const float*)d_in[7];
    const float* wl1 = (const float*)d_in[8];
    const float* wr1 = (const float*)d_in[9];
    const float* b1  = (const float*)d_in[10];
    const float* g1  = (const float*)d_in[11];
    const float* bb1 = (const float*)d_in[12];
    const float* cw1 = (const float*)d_in[13];
    const float* cb1 = (const float*)d_in[14];
    const float* cw2 = (const float*)d_in[15];
    const float* cb2 = (const float*)d_in[16];
    const float* cw3 = (const float*)d_in[17];
    const float* cb3 = (const float*)d_in[18];
    float* out = (float*)d_out;

    const int SCAN_BLOCKS = (N_NODES + 1023) / 1024;  // 98

    detect_kernel<<<1, 32>>>(ei);
    zero_cnt_kernel<<<(N_NODES + 255) / 256, 256>>>();
    hist_kernel<<<(N_EDGES + 255) / 256, 256>>>(ei);
    scan1_kernel<<<SCAN_BLOCKS, 1024>>>();
    scan2_kernel<<<1, 128>>>(SCAN_BLOCKS);
    scan3_kernel<<<(N_NODES + 255) / 256, 256>>>();
    fill_kernel<<<(N_EDGES + 255) / 256, 256>>>(ei);

    sage_kernel<<<1480, 128>>>(x, 0, wl0, wr0, b0, g0, bb0);
    sage_kernel<<<1480, 128>>>(x, 1, wl1, wr1, b1, g1, bb1);
    node_pre_kernel<<<1480, 128>>>(cw1, cb1);

    cudaFuncSetAttribute(edge_mma_kernel,
                         cudaFuncAttributeMaxDynamicSharedMemorySize, EDGE_SMEM_TOTAL);
    edge_mma_kernel<<<296, 512, EDGE_SMEM_TOTAL>>>(
        ei, ea, cw1, cw2, cb2, cw3, cb3, out);
}